// round 14
// baseline (speedup 1.0000x reference)
#include <cuda_runtime.h>
#include <math.h>

#define S 32768

static __device__ float g_qkvt[2*192*S];
static __device__ float g_nrm[2*128];
static __device__ float g_Gpart[2*4*64*256];
static __device__ float g_attn[2*4*256];
static __device__ float g_x5[2*64*S];
static __device__ float g_u[2*64*S];
static __device__ float g_a1[2*64*S];
static __device__ float g_a2[2*64*S];
static __device__ float g_a2t[2*64*S];        // spatial-major [b][s][c]
static __device__ float g_off[2*81*S];
static __device__ float g_dcn[2*64*S];
static __device__ float g_yfin[2*64*S];
static __device__ float g_offw_t[27*96*64];   // [tap][o pad96][c]  (tf32 path)
static __device__ unsigned g_dcnw_bf[27*64*36]; // [tap][o][cpair pad36] bf16x2

__device__ __forceinline__ float* bufptr(int id){
  switch(id){case 0:return g_x5;case 1:return g_u;case 2:return g_a1;
  case 3:return g_a2;case 4:return g_dcn;default:return g_yfin;}
}

__device__ __forceinline__ float tf32r(float x){
  unsigned u; asm("cvt.rna.tf32.f32 %0,%1;":"=r"(u):"f"(x));
  return __uint_as_float(u);
}

__device__ __forceinline__ unsigned packbf(float lo,float hi){
  unsigned u; asm("cvt.rn.bf16x2.f32 %0,%1,%2;":"=r"(u):"f"(hi),"f"(lo));
  return u;
}

__device__ __forceinline__ void mma8(float* d,const unsigned* a,unsigned b0,unsigned b1){
  asm volatile("mma.sync.aligned.m16n8k8.row.col.f32.tf32.tf32.f32 "
    "{%0,%1,%2,%3},{%4,%5,%6,%7},{%8,%9},{%0,%1,%2,%3};"
    :"+f"(d[0]),"+f"(d[1]),"+f"(d[2]),"+f"(d[3])
    :"r"(a[0]),"r"(a[1]),"r"(a[2]),"r"(a[3]),"r"(b0),"r"(b1));
}

__device__ __forceinline__ void mma16(float* d,unsigned a0,unsigned a1,unsigned a2,
    unsigned a3,unsigned b0,unsigned b1){
  asm volatile("mma.sync.aligned.m16n8k16.row.col.f32.bf16.bf16.f32 "
    "{%0,%1,%2,%3},{%4,%5,%6,%7},{%8,%9},{%0,%1,%2,%3};"
    :"+f"(d[0]),"+f"(d[1]),"+f"(d[2]),"+f"(d[3])
    :"r"(a0),"r"(a1),"r"(a2),"r"(a3),"r"(b0),"r"(b1));
}

__global__ void k_wprep(const float* __restrict__ offw,const float* __restrict__ dcnw){
  int t=blockIdx.x*256+threadIdx.x;
  if(t<27*96*64){int k=t/(96*64);int rem=t-k*96*64;int o=rem>>6,c=rem&63;
    g_offw_t[t]=(o<81)?offw[(o*64+c)*27+k]:0.f;}
  if(t<27*64*36){int k=t/2304;int rem=t-k*2304;int o=rem/36,cp=rem-o*36;
    unsigned pw=0;
    if(cp<32){
      float f0=dcnw[(o*64+2*cp)*27+k],f1=dcnw[(o*64+2*cp+1)*27+k];
      pw=packbf(f0,f1);
    }
    g_dcnw_bf[t]=pw;}
}

__global__ __launch_bounds__(256) void k_qkv(const float* __restrict__ x,const float* __restrict__ w){
  __shared__ float xs[64][65],ws[64][65];
  int b=blockIdx.x>>9,n0=(blockIdx.x&511)<<6,t=threadIdx.x;
  const float* xp=x+(b*S+n0)*64;
  for(int i=0;i<16;i++){int e=t+256*i;xs[e>>6][e&63]=xp[e];}
  int ng=t&15,og=t>>4;
  for(int pass=0;pass<3;pass++){
    __syncthreads();
    for(int i=0;i<16;i++){int e=t+256*i;ws[e>>6][e&63]=w[pass*4096+e];}
    __syncthreads();
    float acc[4][4];
    for(int i=0;i<4;i++)for(int m=0;m<4;m++)acc[i][m]=0.f;
    for(int c=0;c<64;c++){
      float xv[4],wv[4];
      #pragma unroll
      for(int m=0;m<4;m++)xv[m]=xs[ng+16*m][c];
      #pragma unroll
      for(int i=0;i<4;i++)wv[i]=ws[og+16*i][c];
      #pragma unroll
      for(int i=0;i<4;i++)
        #pragma unroll
        for(int m=0;m<4;m++)acc[i][m]+=wv[i]*xv[m];
    }
    for(int i=0;i<4;i++){int j=pass*64+og+16*i;
      for(int m=0;m<4;m++)g_qkvt[(b*192+j)*S+n0+ng+16*m]=acc[i][m];}
  }
}

__global__ void k_sumsq(){
  int b=blockIdx.x>>7,j=blockIdx.x&127,t=threadIdx.x;
  const float* row=g_qkvt+(b*192+j)*S;
  float p=0.f;
  for(int i=0;i<128;i++){float v=row[t+256*i];p+=v*v;}
  __shared__ float red[256];
  red[t]=p;__syncthreads();
  for(int st=128;st>0;st>>=1){if(t<st)red[t]+=red[t+st];__syncthreads();}
  if(t==0)g_nrm[b*128+j]=fmaxf(sqrtf(red[0]),1e-12f);
}

__global__ __launch_bounds__(256) void k_gram(){
  __shared__ float qs[16][129],ks[16][129];
  int id=blockIdx.x,chunk=id&63,h=(id>>6)&3,b=id>>8,t=threadIdx.x;
  int c=t>>4,d=t&15,nbase=chunk*512;
  const float* qrow=g_qkvt+(b*192+h*16)*S;
  const float* krow=g_qkvt+(b*192+64+h*16)*S;
  float acc=0.f;
  for(int ch=0;ch<4;ch++){
    int nb=nbase+ch*128;
    __syncthreads();
    for(int i=0;i<16;i++){int e=t+256*i;int r=e>>7,n=e&127;
      if(r<16)qs[r][n]=qrow[r*S+nb+n];else ks[r-16][n]=krow[(r-16)*S+nb+n];}
    __syncthreads();
    for(int n=0;n<128;n++)acc+=qs[c][n]*ks[d][n];
  }
  g_Gpart[((b*4+h)*64+chunk)*256+c*16+d]=acc;
}

__global__ void k_softmax(const float* __restrict__ temp){
  int b=blockIdx.x>>2,h=blockIdx.x&3,t=threadIdx.x;
  int c=t>>4,d=t&15;
  float g=0.f;
  for(int ch=0;ch<64;ch++)g+=g_Gpart[((b*4+h)*64+ch)*256+t];
  float nq=g_nrm[b*128+h*16+c],nk=g_nrm[b*128+64+h*16+d];
  float v=g/(nq*nk)*temp[h];
  float m=v;
  for(int o=8;o;o>>=1)m=fmaxf(m,__shfl_xor_sync(0xffffffffu,m,o,16));
  float e=expf(v-m),s2=e;
  for(int o=8;o;o>>=1)s2+=__shfl_xor_sync(0xffffffffu,s2,o,16);
  g_attn[(b*4+h)*256+c*16+d]=e/s2;
}

__global__ __launch_bounds__(256) void k_xca(const float* __restrict__ nw,const float* __restrict__ nb){
  __shared__ float vs[64][65],xc[64][65],at[1024],mu[64],rs[64];
  int b=blockIdx.x>>9,n0=(blockIdx.x&511)<<6,t=threadIdx.x;
  for(int i=0;i<16;i++){int e=t+256*i;int r=e>>6,n=e&63;
    vs[r][n]=g_qkvt[(b*192+128+r)*S+n0+n];}
  for(int i=0;i<4;i++)at[t+256*i]=g_attn[b*1024+t+256*i];
  __syncthreads();
  int sl=t&63,og=t>>6;
  for(int i=0;i<16;i++){
    float a=0.f;
    const float* ar=at+og*256+i*16;
    #pragma unroll
    for(int d=0;d<16;d++)a+=ar[d]*vs[og*16+d][sl];
    xc[og*16+i][sl]=a;
  }
  __syncthreads();
  if(t<64){
    float s1=0.f;
    for(int c2=0;c2<64;c2++)s1+=xc[c2][t];
    float m=s1*(1.f/64.f),sq=0.f;
    for(int c2=0;c2<64;c2++){float d2=xc[c2][t]-m;sq+=d2*d2;}
    mu[t]=m;rs[t]=rsqrtf(sq*(1.f/64.f)+1e-5f);
  }
  __syncthreads();
  for(int i=0;i<16;i++){int c=og*16+i;
    g_x5[(b*64+c)*S+n0+sl]=(xc[c][sl]-mu[sl])*rs[sl]*nw[c]+nb[c];}
}

template<int MODE>
__global__ __launch_bounds__(256) void k_pw(int inid,int auxid,int outid,
    const float* __restrict__ w,const float* __restrict__ bias){
  __shared__ float xs[64][65],ws2[64][65];
  const float* in=bufptr(inid);const float* aux=bufptr(auxid);float* out=bufptr(outid);
  int b=blockIdx.x>>9,s0=(blockIdx.x&511)<<6,t=threadIdx.x;
  for(int i=0;i<16;i++){int e=t+256*i;int c=e>>6,s=e&63;
    xs[c][s]=in[(b*64+c)*S+s0+s];ws2[c][s]=w[e];}
  __syncthreads();
  int sg=t&15,og=t>>4;
  float acc[4][4];
  for(int i=0;i<4;i++)for(int m=0;m<4;m++)acc[i][m]=0.f;
  for(int c=0;c<64;c++){
    float xv[4],wv[4];
    #pragma unroll
    for(int m=0;m<4;m++)xv[m]=xs[c][sg+16*m];
    #pragma unroll
    for(int i=0;i<4;i++)wv[i]=ws2[og+16*i][c];
    #pragma unroll
    for(int i=0;i<4;i++)
      #pragma unroll
      for(int m=0;m<4;m++)acc[i][m]+=wv[i]*xv[m];
  }
  for(int i=0;i<4;i++){
    int o=og+16*i;float bv=bias[o];
    for(int m=0;m<4;m++){
      int idx=(b*64+o)*S+s0+sg+16*m;
      float v=acc[i][m]+bv;
      if(MODE==1)v=0.5f*v*(1.f+erff(v*0.70710678118654752f));
      if(MODE==2)v*=aux[idx];
      if(MODE==3)v+=aux[idx];
      out[idx]=v;
    }
  }
}

__global__ __launch_bounds__(256) void k_dw5(int inid,int outid,
    const float* __restrict__ wt,const float* __restrict__ bias){
  __shared__ float pl[5][32][37];__shared__ float wsm[125];
  const float* in=bufptr(inid);float* out=bufptr(outid);
  int bc=blockIdx.x>>5,z=blockIdx.x&31,c=bc&63,t=threadIdx.x;
  if(t<125)wsm[t]=wt[c*125+t];
  const float* base=in+bc*S;
  // single pass: padded fill (x origin at 2)
  for(int e=t;e<5*32*37;e+=256){
    int p=e/1184,rem=e-p*1184;
    int y=rem/37,xp=rem-y*37;
    int zz=z+p-2,gx=xp-2;
    float v=0.f;
    if((unsigned)zz<32u&&(unsigned)gx<32u)v=base[zz*1024+y*32+gx];
    pl[p][y][xp]=v;
  }
  __syncthreads();
  int x=t&31,ty=t>>5;
  float bv=bias[c];
  float acc[4]={bv,bv,bv,bv};
  for(int tz=0;tz<5;tz++)
    for(int qy=0;qy<5;qy++){
      float w5[5];
      #pragma unroll
      for(int qx=0;qx<5;qx++)w5[qx]=wsm[(tz*5+qy)*5+qx];
      int yb=qy-2;
      #pragma unroll
      for(int m=0;m<4;m++){
        int yy=ty+8*m+yb;
        if((unsigned)yy<32u){
          #pragma unroll
          for(int qx=0;qx<5;qx++)acc[m]+=w5[qx]*pl[tz][yy][x+qx];
        }
      }
    }
  #pragma unroll
  for(int m=0;m<4;m++)
    out[bc*S+z*1024+(ty+8*m)*32+x]=acc[m];
}

__global__ __launch_bounds__(256) void k_dw7(int inid,int outid,
    const float* __restrict__ wt,const float* __restrict__ bias){
  __shared__ float pl[7][32][52];__shared__ float wsm[343];
  const float* in=bufptr(inid);float* out=bufptr(outid);
  int bc=blockIdx.x>>5,z=blockIdx.x&31,c=bc&63,t=threadIdx.x;
  for(int i=t;i<343;i+=256)wsm[i]=wt[c*343+i];
  const float* base=in+bc*S;
  // single pass: padded fill (x origin at 9)
  for(int e=t;e<7*32*52;e+=256){
    int p=e/1664,rem=e-p*1664;
    int y=rem/52,xp=rem-y*52;
    int zz=z+3*p-9,gx=xp-9;
    float v=0.f;
    if((unsigned)zz<32u&&(unsigned)gx<32u)v=base[zz*1024+y*32+gx];
    pl[p][y][xp]=v;
  }
  __syncthreads();
  int x=t&31,ty=t>>5;
  float bv=bias[c];
  float acc[4]={bv,bv,bv,bv};
  for(int tz=0;tz<7;tz++)
    for(int qy=0;qy<7;qy++){
      float w7[7];
      #pragma unroll
      for(int qx=0;qx<7;qx++)w7[qx]=wsm[(tz*7+qy)*7+qx];
      int yb=3*qy-9;
      #pragma unroll
      for(int m=0;m<4;m++){
        int yy=ty+8*m+yb;
        if((unsigned)yy<32u){
          #pragma unroll
          for(int qx=0;qx<7;qx++)acc[m]+=w7[qx]*pl[tz][yy][x+3*qx];
        }
      }
    }
  #pragma unroll
  for(int m=0;m<4;m++)
    out[bc*S+z*1024+(ty+8*m)*32+x]=acc[m];
}

// tile-transpose a2 [c][s] -> a2t [s][c]
__global__ __launch_bounds__(256) void k_tr(){
  __shared__ float ts[64][65];
  int b=blockIdx.x>>9,s0=(blockIdx.x&511)<<6,t=threadIdx.x;
  for(int i=0;i<16;i++){int e=t+256*i;int c=e>>6,s=e&63;
    ts[c][s]=g_a2[(b*64+c)*S+s0+s];}
  __syncthreads();
  for(int i=0;i<16;i++){int e=t+256*i;int s=e>>6,c=e&63;
    g_a2t[(b*S+s0+s)*64+c]=ts[c][s];}
}

// offset conv via tf32 MMA: M=64 spatial, N=96 outputs, K=27*64
__global__ __launch_bounds__(256) void k_off(const float* __restrict__ offb){
  __shared__ float rows[2][64][34];
  __shared__ float wsm[96*65];
  int blk=blockIdx.x;
  int b=blk>>9,z=(blk>>4)&31,y0=(blk&15)<<1,t=threadIdx.x;
  int w=t>>5,l=t&31;
  int mt=w>>1,nh=w&1;
  int lr=l>>2,lc=l&3;
  float acc[6][4];
  for(int j=0;j<6;j++)for(int q=0;q<4;q++)acc[j][q]=0.f;
  const float* ab=g_a2+b*64*S;
  int sA_=mt*16+lr, sB_=sA_+8;
  int r0=sA_>>5,xa=sA_&31;
  int r1=sB_>>5,xb=sB_&31;
  for(int tz=0;tz<3;tz++){
    int zz=z+tz-1;bool zok=(unsigned)zz<32u;
    for(int ty=0;ty<3;ty++){
      __syncthreads();
      for(int i=0;i<17;i++){
        int e=t+256*i;int r=e/2176,rem=e-r*2176;
        int cc=rem/34,xi=rem-cc*34;
        int yy=y0+ty-1+r,gx=xi-1;
        float v=0.f;
        if(zok&&(unsigned)yy<32u&&(unsigned)gx<32u)v=ab[cc*S+zz*1024+yy*32+gx];
        rows[r][cc][xi]=tf32r(v);
      }
      for(int tx=0;tx<3;tx++){
        int k=(tz*3+ty)*3+tx;
        __syncthreads();
        for(int i=0;i<24;i++){int e=t+256*i;
          wsm[(e>>6)*65+(e&63)]=tf32r(g_offw_t[k*6144+e]);}
        __syncthreads();
        #pragma unroll
        for(int kc=0;kc<8;kc++){
          unsigned a[4];
          int cA=kc*8+lc;
          a[0]=__float_as_uint(rows[r0][cA][xa+tx]);
          a[1]=__float_as_uint(rows[r1][cA][xb+tx]);
          a[2]=__float_as_uint(rows[r0][cA+4][xa+tx]);
          a[3]=__float_as_uint(rows[r1][cA+4][xb+tx]);
          #pragma unroll
          for(int j=0;j<6;j++){
            int o=(nh*6+j)*8+lr;
            unsigned b0=__float_as_uint(wsm[o*65+cA]);
            unsigned b1=__float_as_uint(wsm[o*65+cA+4]);
            mma8(acc[j],a,b0,b1);
          }
        }
      }
    }
  }
  int spA=z*1024+(y0+r0)*32+xa;
  int spB=z*1024+(y0+r1)*32+xb;
  #pragma unroll
  for(int j=0;j<6;j++){
    int ob=(nh*6+j)*8;
    #pragma unroll
    for(int q=0;q<2;q++){
      int o=ob+2*lc+q;
      if(o<81){
        float bv=offb[o];
        g_off[(b*81+o)*S+spA]=acc[j][q]+bv;
        g_off[(b*81+o)*S+spB]=acc[j][q+2]+bv;
      }
    }
  }
}

// deformable conv: per-sp gather + bf16 m16n8k16 MMA
__global__ __launch_bounds__(256) void k_dcn(const float* __restrict__ dcnb){
  extern __shared__ unsigned dynu[];
  unsigned* samp=dynu;                 // [128][36] bf16x2 words
  unsigned* wsm=dynu+128*36;           // [64][36]  bf16x2 words
  float* cw2=(float*)(wsm+64*36);      // [128][8]
  int* ci2=(int*)(cw2+1024);           // [128][8]
  int b=blockIdx.x>>8,s0=(blockIdx.x&255)<<7,t=threadIdx.x;
  int w=t>>5,l=t&31,mt=w>>1,nh=w&1,lr=l>>2,lc=l&3;
  int sp=t>>1,half=t&1;
  float acc[8][4];
  for(int j=0;j<8;j++)for(int q=0;q<4;q++)acc[j][q]=0.f;
  const float* at=g_a2t+(size_t)b*64*S;
  for(int k=0;k<27;k++){
    __syncthreads();
    if(t<128){
      int s=s0+t;
      int z=s>>10,y=(s>>5)&31,x=s&31;
      int kz=k/9,ky=(k/3)%3,kx=k%3;
      float pz=(float)(z+kz-1)+g_off[(b*81+3*k+0)*S+s];
      float py=(float)(y+ky-1)+g_off[(b*81+3*k+1)*S+s];
      float px=(float)(x+kx-1)+g_off[(b*81+3*k+2)*S+s];
      float fz=floorf(pz),fy=floorf(py),fx=floorf(px);
      float wz=pz-fz,wy=py-fy,wx=px-fx;
      int z0=(int)fz,y0=(int)fy,x0=(int)fx;
      #pragma unroll
      for(int cn=0;cn<8;cn++){
        int dz=cn>>2,dy=(cn>>1)&1,dx=cn&1;
        int iz=z0+dz,iy=y0+dy,ix=x0+dx;
        float wv=(dz?wz:1.f-wz)*(dy?wy:1.f-wy)*(dx?wx:1.f-wx);
        bool ok=(unsigned)iz<32u&&(unsigned)iy<32u&&(unsigned)ix<32u;
        int czi=min(max(iz,0),31),cyi=min(max(iy,0),31),cxi=min(max(ix,0),31);
        cw2[t*8+cn]=ok?wv:0.f;
        ci2[t*8+cn]=(czi*32+cyi)*32+cxi;
      }
    }
    for(int i=0;i<9;i++){int e=t+256*i;if(e<2304)wsm[e]=g_dcnw_bf[k*2304+e];}
    __syncthreads();
    // gather: thread owns (sp, 32-channel half); corner data read once
    float g32[32];
    #pragma unroll
    for(int i=0;i<32;i++)g32[i]=0.f;
    #pragma unroll
    for(int cn=0;cn<8;cn++){
      float wv=cw2[sp*8+cn];
      const float4* p=(const float4*)(at+(size_t)ci2[sp*8+cn]*64+half*32);
      #pragma unroll
      for(int g=0;g<8;g++){
        float4 v=p[g];
        g32[g*4+0]+=wv*v.x;g32[g*4+1]+=wv*v.y;
        g32[g*4+2]+=wv*v.z;g32[g*4+3]+=wv*v.w;
      }
    }
    unsigned* srow=samp+sp*36+half*16;
    #pragma unroll
    for(int g=0;g<16;g++)srow[g]=packbf(g32[2*g],g32[2*g+1]);
    __syncthreads();
    int oA=mt*16+lr;
    #pragma unroll
    for(int kc=0;kc<4;kc++){
      unsigned a0=wsm[(oA  )*36+kc*8+lc];
      unsigned a1=wsm[(oA+8)*36+kc*8+lc];
      unsigned a2v=wsm[(oA  )*36+kc*8+lc+4];
      unsigned a3=wsm[(oA+8)*36+kc*8+lc+4];
      #pragma unroll
      for(int j=0;j<8;j++){
        int spc=(nh*8+j)*8+lr;
        unsigned b0=samp[spc*36+kc*8+lc];
        unsigned b1=samp[spc*36+kc*8+lc+4];
        mma16(acc[j],a0,a1,a2v,a3,b0,b1);
      }
    }
  }
  int oA=mt*16+lr;
  float bv0=dcnb[oA],bv1=dcnb[oA+8];
  #pragma unroll
  for(int j=0;j<8;j++){
    int spb=(nh*8+j)*8;
    #pragma unroll
    for(int q=0;q<2;q++){
      int spc=spb+2*lc+q;
      g_dcn[(b*64+oA)*S+s0+spc]=acc[j][q]+bv0;
      g_dcn[(b*64+oA+8)*S+s0+spc]=acc[j][q+2]+bv1;
    }
  }
}

__global__ __launch_bounds__(256) void k_final(const float* __restrict__ n2w,
    const float* __restrict__ n2b,const float* __restrict__ ow,
    const float* __restrict__ ob,float* __restrict__ out){
  __shared__ float Msm[64][65],wsm[64][65],mu[64],rs[64];
  int b=blockIdx.x>>9,g=blockIdx.x&511,t=threadIdx.x;
  for(int i=0;i<16;i++){int e=t+256*i;int r=e>>6,p=e&63;
    Msm[r][p]=g_yfin[(b*64+r)*S+g+(p<<9)];
    wsm[r][p]=ow[e];}
  __syncthreads();
  if(t<64){
    float s1=0.f;
    for(int p=0;p<64;p++)s1+=Msm[t][p];
    float m=s1*(1.f/64.f),sq=0.f;
    for(int p=0;p<64;p++){float d=Msm[t][p]-m;sq+=d*d;}
    mu[t]=m;rs[t]=rsqrtf(sq*(1.f/64.f)+1e-5f);
  }
  __syncthreads();
  for(int i=0;i<16;i++){int e=t+256*i;int r=e>>6,p=e&63;
    Msm[r][p]=(Msm[r][p]-mu[r])*rs[r]*n2w[p]+n2b[p];}
  __syncthreads();
  int og=t&15,sg=t>>4;
  float acc[4][4];
  for(int m=0;m<4;m++)for(int i=0;i<4;i++)acc[m][i]=0.f;
  for(int p=0;p<64;p++){
    float xv[4],wv[4];
    #pragma unroll
    for(int m=0;m<4;m++)xv[m]=Msm[sg+16*m][p];
    #pragma unroll
    for(int i=0;i<4;i++)wv[i]=wsm[og+16*i][p];
    #pragma unroll
    for(int m=0;m<4;m++)
      #pragma unroll
      for(int i=0;i<4;i++)acc[m][i]+=xv[m]*wv[i];
  }
  for(int m=0;m<4;m++){
    int q=(g<<6)+sg+16*m;
    for(int i=0;i<4;i++){
      int o=og+16*i;
      out[(b*S+q)*64+o]=acc[m][i]+ob[o];
    }
  }
}

extern "C" void kernel_launch(void* const* d_in,const int* in_sizes,int n_in,
                              void* d_out,int out_size){
  const float* x   =(const float*)d_in[0];
  const float* temp=(const float*)d_in[1];
  const float* qkvw=(const float*)d_in[2];
  const float* nw  =(const float*)d_in[3];
  const float* nb  =(const float*)d_in[4];
  const float* p1w =(const float*)d_in[5];
  const float* p1b =(const float*)d_in[6];
  const float* c0w =(const float*)d_in[7];
  const float* c0b =(const float*)d_in[8];
  const float* cspw=(const float*)d_in[9];
  const float* cspb=(const float*)d_in[10];
  const float* offw=(const float*)d_in[11];
  const float* offb=(const float*)d_in[12];
  const float* dcnw=(const float*)d_in[13];
  const float* dcnb=(const float*)d_in[14];
  const float* c1w =(const float*)d_in[15];
  const float* c1b =(const float*)d_in[16];
  const float* p2w =(const float*)d_in[17];
  const float* p2b =(const float*)d_in[18];
  const float* n2w =(const float*)d_in[19];
  const float* n2b =(const float*)d_in[20];
  const float* ow  =(const float*)d_in[21];
  const float* ob  =(const float*)d_in[22];
  float* out=(float*)d_out;

  int dcn_smem=(128*36+64*36+1024+1024)*4;  // 35840 B
  cudaFuncSetAttribute(k_dcn,cudaFuncAttributeMaxDynamicSharedMemorySize,dcn_smem);

  k_wprep<<<648,256>>>(offw,dcnw);
  k_qkv<<<1024,256>>>(x,qkvw);
  k_sumsq<<<256,256>>>();
  k_gram<<<512,256>>>();
  k_softmax<<<8,256>>>(temp);
  k_xca<<<1024,256>>>(nw,nb);
  k_pw<1><<<1024,256>>>(0,0,1,p1w,p1b);   // u = gelu(proj1(x5))
  k_dw5<<<4096,256>>>(1,2,c0w,c0b);       // a1 = dw5(u)
  k_dw7<<<4096,256>>>(2,3,cspw,cspb);     // a2 = dw7(a1)
  k_tr<<<1024,256>>>();                   // a2 -> a2t (spatial-major)
  k_off<<<1024,256>>>(offb);              // offsets from a2 (tf32 MMA)
  k_dcn<<<512,256,dcn_smem>>>(dcnb);      // deformable conv (bf16 MMA)
  k_pw<2><<<1024,256>>>(4,1,2,c1w,c1b);   // a1 = (conv1(dcn)+b)*u
  k_pw<3><<<1024,256>>>(2,0,5,p2w,p2b);   // yfin = proj2(a1)+x5
  k_final<<<1024,256>>>(n2w,n2b,ow,ob,out);
}

// round 15
// speedup vs baseline: 1.5188x; 1.5188x over previous
#include <cuda_runtime.h>
#include <math.h>

#define S 32768

static __device__ float g_qkvt[2*192*S];
static __device__ float g_nrm[2*128];
static __device__ float g_Gpart[2*4*64*256];
static __device__ float g_attn[2*4*256];
static __device__ float g_x5[2*64*S];
static __device__ float g_u[2*64*S];
static __device__ float g_a1[2*64*S];
static __device__ float g_a2[2*64*S];
static __device__ float g_a2t[2*64*S];        // spatial-major [b][s][c]
static __device__ float g_off[2*81*S];
static __device__ float g_dcn[2*64*S];
static __device__ float g_yfin[2*64*S];
static __device__ float g_offw_t[27*96*64];   // [tap][o pad96][c]  (tf32 path)
static __device__ unsigned g_dcnw_bf[27*64*36]; // [tap][o][cpair pad36] bf16x2

__device__ __forceinline__ float* bufptr(int id){
  switch(id){case 0:return g_x5;case 1:return g_u;case 2:return g_a1;
  case 3:return g_a2;case 4:return g_dcn;default:return g_yfin;}
}

__device__ __forceinline__ float tf32r(float x){
  unsigned u; asm("cvt.rna.tf32.f32 %0,%1;":"=r"(u):"f"(x));
  return __uint_as_float(u);
}

__device__ __forceinline__ unsigned packbf(float lo,float hi){
  unsigned u; asm("cvt.rn.bf16x2.f32 %0,%1,%2;":"=r"(u):"f"(hi),"f"(lo));
  return u;
}

__device__ __forceinline__ void mma8(float* d,const unsigned* a,unsigned b0,unsigned b1){
  asm volatile("mma.sync.aligned.m16n8k8.row.col.f32.tf32.tf32.f32 "
    "{%0,%1,%2,%3},{%4,%5,%6,%7},{%8,%9},{%0,%1,%2,%3};"
    :"+f"(d[0]),"+f"(d[1]),"+f"(d[2]),"+f"(d[3])
    :"r"(a[0]),"r"(a[1]),"r"(a[2]),"r"(a[3]),"r"(b0),"r"(b1));
}

__device__ __forceinline__ void mma16(float* d,unsigned a0,unsigned a1,unsigned a2,
    unsigned a3,unsigned b0,unsigned b1){
  asm volatile("mma.sync.aligned.m16n8k16.row.col.f32.bf16.bf16.f32 "
    "{%0,%1,%2,%3},{%4,%5,%6,%7},{%8,%9},{%0,%1,%2,%3};"
    :"+f"(d[0]),"+f"(d[1]),"+f"(d[2]),"+f"(d[3])
    :"r"(a0),"r"(a1),"r"(a2),"r"(a3),"r"(b0),"r"(b1));
}

__global__ void k_wprep(const float* __restrict__ offw,const float* __restrict__ dcnw){
  int t=blockIdx.x*256+threadIdx.x;
  if(t<27*96*64){int k=t/(96*64);int rem=t-k*96*64;int o=rem>>6,c=rem&63;
    g_offw_t[t]=(o<81)?offw[(o*64+c)*27+k]:0.f;}
  if(t<27*64*36){int k=t/2304;int rem=t-k*2304;int o=rem/36,cp=rem-o*36;
    unsigned pw=0;
    if(cp<32){
      float f0=dcnw[(o*64+2*cp)*27+k],f1=dcnw[(o*64+2*cp+1)*27+k];
      pw=packbf(f0,f1);
    }
    g_dcnw_bf[t]=pw;}
}

__global__ __launch_bounds__(256) void k_qkv(const float* __restrict__ x,const float* __restrict__ w){
  __shared__ float xs[64][65],ws[64][65];
  int b=blockIdx.x>>9,n0=(blockIdx.x&511)<<6,t=threadIdx.x;
  const float* xp=x+(b*S+n0)*64;
  for(int i=0;i<16;i++){int e=t+256*i;xs[e>>6][e&63]=xp[e];}
  int ng=t&15,og=t>>4;
  for(int pass=0;pass<3;pass++){
    __syncthreads();
    for(int i=0;i<16;i++){int e=t+256*i;ws[e>>6][e&63]=w[pass*4096+e];}
    __syncthreads();
    float acc[4][4];
    for(int i=0;i<4;i++)for(int m=0;m<4;m++)acc[i][m]=0.f;
    for(int c=0;c<64;c++){
      float xv[4],wv[4];
      #pragma unroll
      for(int m=0;m<4;m++)xv[m]=xs[ng+16*m][c];
      #pragma unroll
      for(int i=0;i<4;i++)wv[i]=ws[og+16*i][c];
      #pragma unroll
      for(int i=0;i<4;i++)
        #pragma unroll
        for(int m=0;m<4;m++)acc[i][m]+=wv[i]*xv[m];
    }
    for(int i=0;i<4;i++){int j=pass*64+og+16*i;
      for(int m=0;m<4;m++)g_qkvt[(b*192+j)*S+n0+ng+16*m]=acc[i][m];}
  }
}

__global__ void k_sumsq(){
  int b=blockIdx.x>>7,j=blockIdx.x&127,t=threadIdx.x;
  const float* row=g_qkvt+(b*192+j)*S;
  float p=0.f;
  for(int i=0;i<128;i++){float v=row[t+256*i];p+=v*v;}
  __shared__ float red[256];
  red[t]=p;__syncthreads();
  for(int st=128;st>0;st>>=1){if(t<st)red[t]+=red[t+st];__syncthreads();}
  if(t==0)g_nrm[b*128+j]=fmaxf(sqrtf(red[0]),1e-12f);
}

__global__ __launch_bounds__(256) void k_gram(){
  __shared__ float qs[16][129],ks[16][129];
  int id=blockIdx.x,chunk=id&63,h=(id>>6)&3,b=id>>8,t=threadIdx.x;
  int c=t>>4,d=t&15,nbase=chunk*512;
  const float* qrow=g_qkvt+(b*192+h*16)*S;
  const float* krow=g_qkvt+(b*192+64+h*16)*S;
  float acc=0.f;
  for(int ch=0;ch<4;ch++){
    int nb=nbase+ch*128;
    __syncthreads();
    for(int i=0;i<16;i++){int e=t+256*i;int r=e>>7,n=e&127;
      if(r<16)qs[r][n]=qrow[r*S+nb+n];else ks[r-16][n]=krow[(r-16)*S+nb+n];}
    __syncthreads();
    for(int n=0;n<128;n++)acc+=qs[c][n]*ks[d][n];
  }
  g_Gpart[((b*4+h)*64+chunk)*256+c*16+d]=acc;
}

__global__ void k_softmax(const float* __restrict__ temp){
  int b=blockIdx.x>>2,h=blockIdx.x&3,t=threadIdx.x;
  int c=t>>4,d=t&15;
  float g=0.f;
  for(int ch=0;ch<64;ch++)g+=g_Gpart[((b*4+h)*64+ch)*256+t];
  float nq=g_nrm[b*128+h*16+c],nk=g_nrm[b*128+64+h*16+d];
  float v=g/(nq*nk)*temp[h];
  float m=v;
  for(int o=8;o;o>>=1)m=fmaxf(m,__shfl_xor_sync(0xffffffffu,m,o,16));
  float e=expf(v-m),s2=e;
  for(int o=8;o;o>>=1)s2+=__shfl_xor_sync(0xffffffffu,s2,o,16);
  g_attn[(b*4+h)*256+c*16+d]=e/s2;
}

__global__ __launch_bounds__(256) void k_xca(const float* __restrict__ nw,const float* __restrict__ nb){
  __shared__ float vs[64][65],xc[64][65],at[1024],mu[64],rs[64];
  int b=blockIdx.x>>9,n0=(blockIdx.x&511)<<6,t=threadIdx.x;
  for(int i=0;i<16;i++){int e=t+256*i;int r=e>>6,n=e&63;
    vs[r][n]=g_qkvt[(b*192+128+r)*S+n0+n];}
  for(int i=0;i<4;i++)at[t+256*i]=g_attn[b*1024+t+256*i];
  __syncthreads();
  int sl=t&63,og=t>>6;
  for(int i=0;i<16;i++){
    float a=0.f;
    const float* ar=at+og*256+i*16;
    #pragma unroll
    for(int d=0;d<16;d++)a+=ar[d]*vs[og*16+d][sl];
    xc[og*16+i][sl]=a;
  }
  __syncthreads();
  if(t<64){
    float s1=0.f;
    for(int c2=0;c2<64;c2++)s1+=xc[c2][t];
    float m=s1*(1.f/64.f),sq=0.f;
    for(int c2=0;c2<64;c2++){float d2=xc[c2][t]-m;sq+=d2*d2;}
    mu[t]=m;rs[t]=rsqrtf(sq*(1.f/64.f)+1e-5f);
  }
  __syncthreads();
  for(int i=0;i<16;i++){int c=og*16+i;
    g_x5[(b*64+c)*S+n0+sl]=(xc[c][sl]-mu[sl])*rs[sl]*nw[c]+nb[c];}
}

template<int MODE>
__global__ __launch_bounds__(256) void k_pw(int inid,int auxid,int outid,
    const float* __restrict__ w,const float* __restrict__ bias){
  __shared__ float xs[64][65],ws2[64][65];
  const float* in=bufptr(inid);const float* aux=bufptr(auxid);float* out=bufptr(outid);
  int b=blockIdx.x>>9,s0=(blockIdx.x&511)<<6,t=threadIdx.x;
  for(int i=0;i<16;i++){int e=t+256*i;int c=e>>6,s=e&63;
    xs[c][s]=in[(b*64+c)*S+s0+s];ws2[c][s]=w[e];}
  __syncthreads();
  int sg=t&15,og=t>>4;
  float acc[4][4];
  for(int i=0;i<4;i++)for(int m=0;m<4;m++)acc[i][m]=0.f;
  for(int c=0;c<64;c++){
    float xv[4],wv[4];
    #pragma unroll
    for(int m=0;m<4;m++)xv[m]=xs[c][sg+16*m];
    #pragma unroll
    for(int i=0;i<4;i++)wv[i]=ws2[og+16*i][c];
    #pragma unroll
    for(int i=0;i<4;i++)
      #pragma unroll
      for(int m=0;m<4;m++)acc[i][m]+=wv[i]*xv[m];
  }
  for(int i=0;i<4;i++){
    int o=og+16*i;float bv=bias[o];
    for(int m=0;m<4;m++){
      int idx=(b*64+o)*S+s0+sg+16*m;
      float v=acc[i][m]+bv;
      if(MODE==1)v=0.5f*v*(1.f+erff(v*0.70710678118654752f));
      if(MODE==2)v*=aux[idx];
      if(MODE==3)v+=aux[idx];
      out[idx]=v;
    }
  }
}

__global__ __launch_bounds__(256) void k_dw5(int inid,int outid,
    const float* __restrict__ wt,const float* __restrict__ bias){
  __shared__ float pl[5][32][37];__shared__ float wsm[125];
  const float* in=bufptr(inid);float* out=bufptr(outid);
  int bc=blockIdx.x>>5,z=blockIdx.x&31,c=bc&63,t=threadIdx.x;
  if(t<125)wsm[t]=wt[c*125+t];
  const float* base=in+bc*S;
  for(int e=t;e<5*32*37;e+=256){
    int p=e/1184,rem=e-p*1184;
    int y=rem/37,xp=rem-y*37;
    int zz=z+p-2,gx=xp-2;
    float v=0.f;
    if((unsigned)zz<32u&&(unsigned)gx<32u)v=base[zz*1024+y*32+gx];
    pl[p][y][xp]=v;
  }
  __syncthreads();
  int x=t&31,ty=t>>5;
  float bv=bias[c];
  float acc[4]={bv,bv,bv,bv};
  for(int tz=0;tz<5;tz++)
    for(int qy=0;qy<5;qy++){
      float w5[5];
      #pragma unroll
      for(int qx=0;qx<5;qx++)w5[qx]=wsm[(tz*5+qy)*5+qx];
      int yb=qy-2;
      #pragma unroll
      for(int m=0;m<4;m++){
        int yy=ty+8*m+yb;
        if((unsigned)yy<32u){
          #pragma unroll
          for(int qx=0;qx<5;qx++)acc[m]+=w5[qx]*pl[tz][yy][x+qx];
        }
      }
    }
  #pragma unroll
  for(int m=0;m<4;m++)
    out[bc*S+z*1024+(ty+8*m)*32+x]=acc[m];
}

__global__ __launch_bounds__(256) void k_dw7(int inid,int outid,
    const float* __restrict__ wt,const float* __restrict__ bias){
  __shared__ float pl[7][32][52];__shared__ float wsm[343];
  const float* in=bufptr(inid);float* out=bufptr(outid);
  int bc=blockIdx.x>>5,z=blockIdx.x&31,c=bc&63,t=threadIdx.x;
  for(int i=t;i<343;i+=256)wsm[i]=wt[c*343+i];
  const float* base=in+bc*S;
  for(int e=t;e<7*32*52;e+=256){
    int p=e/1664,rem=e-p*1664;
    int y=rem/52,xp=rem-y*52;
    int zz=z+3*p-9,gx=xp-9;
    float v=0.f;
    if((unsigned)zz<32u&&(unsigned)gx<32u)v=base[zz*1024+y*32+gx];
    pl[p][y][xp]=v;
  }
  __syncthreads();
  int x=t&31,ty=t>>5;
  float bv=bias[c];
  float acc[4]={bv,bv,bv,bv};
  for(int tz=0;tz<7;tz++)
    for(int qy=0;qy<7;qy++){
      float w7[7];
      #pragma unroll
      for(int qx=0;qx<7;qx++)w7[qx]=wsm[(tz*7+qy)*7+qx];
      int yb=3*qy-9;
      #pragma unroll
      for(int m=0;m<4;m++){
        int yy=ty+8*m+yb;
        if((unsigned)yy<32u){
          #pragma unroll
          for(int qx=0;qx<7;qx++)acc[m]+=w7[qx]*pl[tz][yy][x+3*qx];
        }
      }
    }
  #pragma unroll
  for(int m=0;m<4;m++)
    out[bc*S+z*1024+(ty+8*m)*32+x]=acc[m];
}

// tile-transpose a2 [c][s] -> a2t [s][c]
__global__ __launch_bounds__(256) void k_tr(){
  __shared__ float ts[64][65];
  int b=blockIdx.x>>9,s0=(blockIdx.x&511)<<6,t=threadIdx.x;
  for(int i=0;i<16;i++){int e=t+256*i;int c=e>>6,s=e&63;
    ts[c][s]=g_a2[(b*64+c)*S+s0+s];}
  __syncthreads();
  for(int i=0;i<16;i++){int e=t+256*i;int s=e>>6,c=e&63;
    g_a2t[(b*S+s0+s)*64+c]=ts[c][s];}
}

// offset conv via tf32 MMA: M=64 spatial, N=96 outputs, K=27*64
__global__ __launch_bounds__(256) void k_off(const float* __restrict__ offb){
  __shared__ float rows[2][64][34];
  __shared__ float wsm[96*65];
  int blk=blockIdx.x;
  int b=blk>>9,z=(blk>>4)&31,y0=(blk&15)<<1,t=threadIdx.x;
  int w=t>>5,l=t&31;
  int mt=w>>1,nh=w&1;
  int lr=l>>2,lc=l&3;
  float acc[6][4];
  for(int j=0;j<6;j++)for(int q=0;q<4;q++)acc[j][q]=0.f;
  const float* ab=g_a2+b*64*S;
  int sA_=mt*16+lr, sB_=sA_+8;
  int r0=sA_>>5,xa=sA_&31;
  int r1=sB_>>5,xb=sB_&31;
  for(int tz=0;tz<3;tz++){
    int zz=z+tz-1;bool zok=(unsigned)zz<32u;
    for(int ty=0;ty<3;ty++){
      __syncthreads();
      for(int i=0;i<17;i++){
        int e=t+256*i;int r=e/2176,rem=e-r*2176;
        int cc=rem/34,xi=rem-cc*34;
        int yy=y0+ty-1+r,gx=xi-1;
        float v=0.f;
        if(zok&&(unsigned)yy<32u&&(unsigned)gx<32u)v=ab[cc*S+zz*1024+yy*32+gx];
        rows[r][cc][xi]=tf32r(v);
      }
      for(int tx=0;tx<3;tx++){
        int k=(tz*3+ty)*3+tx;
        __syncthreads();
        for(int i=0;i<24;i++){int e=t+256*i;
          wsm[(e>>6)*65+(e&63)]=tf32r(g_offw_t[k*6144+e]);}
        __syncthreads();
        #pragma unroll
        for(int kc=0;kc<8;kc++){
          unsigned a[4];
          int cA=kc*8+lc;
          a[0]=__float_as_uint(rows[r0][cA][xa+tx]);
          a[1]=__float_as_uint(rows[r1][cA][xb+tx]);
          a[2]=__float_as_uint(rows[r0][cA+4][xa+tx]);
          a[3]=__float_as_uint(rows[r1][cA+4][xb+tx]);
          #pragma unroll
          for(int j=0;j<6;j++){
            int o=(nh*6+j)*8+lr;
            unsigned b0=__float_as_uint(wsm[o*65+cA]);
            unsigned b1=__float_as_uint(wsm[o*65+cA+4]);
            mma8(acc[j],a,b0,b1);
          }
        }
      }
    }
  }
  int spA=z*1024+(y0+r0)*32+xa;
  int spB=z*1024+(y0+r1)*32+xb;
  #pragma unroll
  for(int j=0;j<6;j++){
    int ob=(nh*6+j)*8;
    #pragma unroll
    for(int q=0;q<2;q++){
      int o=ob+2*lc+q;
      if(o<81){
        float bv=offb[o];
        g_off[(b*81+o)*S+spA]=acc[j][q]+bv;
        g_off[(b*81+o)*S+spB]=acc[j][q+2]+bv;
      }
    }
  }
}

// deformable conv: coalesced gather (R13 mapping) + bf16 m16n8k16 MMA
__global__ __launch_bounds__(256) void k_dcn(const float* __restrict__ dcnb){
  extern __shared__ unsigned dynu[];
  unsigned* samp=dynu;                 // [128][36] bf16x2 words
  unsigned* wsm=dynu+128*36;           // [64][36]  bf16x2 words
  float* cw=(float*)(wsm+64*36);       // [8][128]
  int* ci=(int*)(cw+1024);             // [8][128]
  int b=blockIdx.x>>8,s0=(blockIdx.x&255)<<7,t=threadIdx.x;
  int w=t>>5,l=t&31,mt=w>>1,nh=w&1,lr=l>>2,lc=l&3;
  float acc[8][4];
  for(int j=0;j<8;j++)for(int q=0;q<4;q++)acc[j][q]=0.f;
  const float* at=g_a2t+(size_t)b*64*S;
  for(int k=0;k<27;k++){
    __syncthreads();
    if(t<128){
      int s=s0+t;
      int z=s>>10,y=(s>>5)&31,x=s&31;
      int kz=k/9,ky=(k/3)%3,kx=k%3;
      float pz=(float)(z+kz-1)+g_off[(b*81+3*k+0)*S+s];
      float py=(float)(y+ky-1)+g_off[(b*81+3*k+1)*S+s];
      float px=(float)(x+kx-1)+g_off[(b*81+3*k+2)*S+s];
      float fz=floorf(pz),fy=floorf(py),fx=floorf(px);
      float wz=pz-fz,wy=py-fy,wx=px-fx;
      int z0=(int)fz,y0=(int)fy,x0=(int)fx;
      #pragma unroll
      for(int cn=0;cn<8;cn++){
        int dz=cn>>2,dy=(cn>>1)&1,dx=cn&1;
        int iz=z0+dz,iy=y0+dy,ix=x0+dx;
        float wv=(dz?wz:1.f-wz)*(dy?wy:1.f-wy)*(dx?wx:1.f-wx);
        bool ok=(unsigned)iz<32u&&(unsigned)iy<32u&&(unsigned)ix<32u;
        int czi=min(max(iz,0),31),cyi=min(max(iy,0),31),cxi=min(max(ix,0),31);
        cw[cn*128+t]=ok?wv:0.f;
        ci[cn*128+t]=(czi*32+cyi)*32+cxi;
      }
    }
    for(int i=0;i<9;i++){int e=t+256*i;if(e<2304)wsm[e]=g_dcnw_bf[k*2304+e];}
    __syncthreads();
    // gather: thread -> (sp, 4-channel quad); coalesced float4 loads
    #pragma unroll
    for(int i=0;i<8;i++){
      int e=t+256*i;int sp=e>>4,q=(e&15)<<2;
      float ax=0.f,ay=0.f,az=0.f,aw=0.f;
      #pragma unroll
      for(int cn=0;cn<8;cn++){
        float wv=cw[cn*128+sp];
        const float4 v4=*(const float4*)(at+(size_t)ci[cn*128+sp]*64+q);
        ax+=wv*v4.x;ay+=wv*v4.y;az+=wv*v4.z;aw+=wv*v4.w;
      }
      unsigned* sw=samp+sp*36+(q>>1);
      sw[0]=packbf(ax,ay);
      sw[1]=packbf(az,aw);
    }
    __syncthreads();
    int oA=mt*16+lr;
    #pragma unroll
    for(int kc=0;kc<4;kc++){
      unsigned a0=wsm[(oA  )*36+kc*8+lc];
      unsigned a1=wsm[(oA+8)*36+kc*8+lc];
      unsigned a2v=wsm[(oA  )*36+kc*8+lc+4];
      unsigned a3=wsm[(oA+8)*36+kc*8+lc+4];
      #pragma unroll
      for(int j=0;j<8;j++){
        int spc=(nh*8+j)*8+lr;
        unsigned b0=samp[spc*36+kc*8+lc];
        unsigned b1=samp[spc*36+kc*8+lc+4];
        mma16(acc[j],a0,a1,a2v,a3,b0,b1);
      }
    }
  }
  int oA=mt*16+lr;
  float bv0=dcnb[oA],bv1=dcnb[oA+8];
  #pragma unroll
  for(int j=0;j<8;j++){
    int spb=(nh*8+j)*8;
    #pragma unroll
    for(int q=0;q<2;q++){
      int spc=spb+2*lc+q;
      g_dcn[(b*64+oA)*S+s0+spc]=acc[j][q]+bv0;
      g_dcn[(b*64+oA+8)*S+s0+spc]=acc[j][q+2]+bv1;
    }
  }
}

__global__ __launch_bounds__(256) void k_final(const float* __restrict__ n2w,
    const float* __restrict__ n2b,const float* __restrict__ ow,
    const float* __restrict__ ob,float* __restrict__ out){
  __shared__ float Msm[64][65],wsm[64][65],mu[64],rs[64];
  int b=blockIdx.x>>9,g=blockIdx.x&511,t=threadIdx.x;
  for(int i=0;i<16;i++){int e=t+256*i;int r=e>>6,p=e&63;
    Msm[r][p]=g_yfin[(b*64+r)*S+g+(p<<9)];
    wsm[r][p]=ow[e];}
  __syncthreads();
  if(t<64){
    float s1=0.f;
    for(int p=0;p<64;p++)s1+=Msm[t][p];
    float m=s1*(1.f/64.f),sq=0.f;
    for(int p=0;p<64;p++){float d=Msm[t][p]-m;sq+=d*d;}
    mu[t]=m;rs[t]=rsqrtf(sq*(1.f/64.f)+1e-5f);
  }
  __syncthreads();
  for(int i=0;i<16;i++){int e=t+256*i;int r=e>>6,p=e&63;
    Msm[r][p]=(Msm[r][p]-mu[r])*rs[r]*n2w[p]+n2b[p];}
  __syncthreads();
  int og=t&15,sg=t>>4;
  float acc[4][4];
  for(int m=0;m<4;m++)for(int i=0;i<4;i++)acc[m][i]=0.f;
  for(int p=0;p<64;p++){
    float xv[4],wv[4];
    #pragma unroll
    for(int m=0;m<4;m++)xv[m]=Msm[sg+16*m][p];
    #pragma unroll
    for(int i=0;i<4;i++)wv[i]=wsm[og+16*i][p];
    #pragma unroll
    for(int m=0;m<4;m++)
      #pragma unroll
      for(int i=0;i<4;i++)acc[m][i]+=xv[m]*wv[i];
  }
  for(int m=0;m<4;m++){
    int q=(g<<6)+sg+16*m;
    for(int i=0;i<4;i++){
      int o=og+16*i;
      out[(b*S+q)*64+o]=acc[m][i]+ob[o];
    }
  }
}

extern "C" void kernel_launch(void* const* d_in,const int* in_sizes,int n_in,
                              void* d_out,int out_size){
  const float* x   =(const float*)d_in[0];
  const float* temp=(const float*)d_in[1];
  const float* qkvw=(const float*)d_in[2];
  const float* nw  =(const float*)d_in[3];
  const float* nb  =(const float*)d_in[4];
  const float* p1w =(const float*)d_in[5];
  const float* p1b =(const float*)d_in[6];
  const float* c0w =(const float*)d_in[7];
  const float* c0b =(const float*)d_in[8];
  const float* cspw=(const float*)d_in[9];
  const float* cspb=(const float*)d_in[10];
  const float* offw=(const float*)d_in[11];
  const float* offb=(const float*)d_in[12];
  const float* dcnw=(const float*)d_in[13];
  const float* dcnb=(const float*)d_in[14];
  const float* c1w =(const float*)d_in[15];
  const float* c1b =(const float*)d_in[16];
  const float* p2w =(const float*)d_in[17];
  const float* p2b =(const float*)d_in[18];
  const float* n2w =(const float*)d_in[19];
  const float* n2b =(const float*)d_in[20];
  const float* ow  =(const float*)d_in[21];
  const float* ob  =(const float*)d_in[22];
  float* out=(float*)d_out;

  int dcn_smem=(128*36+64*36+1024+1024)*4;  // 35840 B
  cudaFuncSetAttribute(k_dcn,cudaFuncAttributeMaxDynamicSharedMemorySize,dcn_smem);

  k_wprep<<<648,256>>>(offw,dcnw);
  k_qkv<<<1024,256>>>(x,qkvw);
  k_sumsq<<<256,256>>>();
  k_gram<<<512,256>>>();
  k_softmax<<<8,256>>>(temp);
  k_xca<<<1024,256>>>(nw,nb);
  k_pw<1><<<1024,256>>>(0,0,1,p1w,p1b);   // u = gelu(proj1(x5))
  k_dw5<<<4096,256>>>(1,2,c0w,c0b);       // a1 = dw5(u)
  k_dw7<<<4096,256>>>(2,3,cspw,cspb);     // a2 = dw7(a1)
  k_tr<<<1024,256>>>();                   // a2 -> a2t (spatial-major)
  k_off<<<1024,256>>>(offb);              // offsets from a2 (tf32 MMA)
  k_dcn<<<512,256,dcn_smem>>>(dcnb);      // deformable conv (bf16 MMA)
  k_pw<2><<<1024,256>>>(4,1,2,c1w,c1b);   // a1 = (conv1(dcn)+b)*u
  k_pw<3><<<1024,256>>>(2,0,5,p2w,p2b);   // yfin = proj2(a1)+x5
  k_final<<<1024,256>>>(n2w,n2b,ow,ob,out);
}

// round 16
// speedup vs baseline: 2.0851x; 1.3729x over previous
#include <cuda_runtime.h>
#include <math.h>

#define S 32768

static __device__ float g_qkvt[2*192*S];
static __device__ float g_nrmp[2*128*8];
static __device__ float g_Gpart[2*4*64*256];
static __device__ float g_attn[2*4*256];
static __device__ float g_x5[2*64*S];
static __device__ float g_u[2*64*S];
static __device__ float g_a1[2*64*S];
static __device__ float g_a2[2*64*S];
static __device__ float g_a2t[2*64*S];          // spatial-major [b][s][c]
static __device__ float g_off[2*81*S];
static __device__ float g_dcn[2*64*S];
static __device__ float g_yfin[2*64*S];
static __device__ unsigned g_offw_bf[27*96*36]; // [tap][o pad96][cpair pad36] bf16x2
static __device__ unsigned g_dcnw_bf[27*64*36]; // [tap][o][cpair pad36] bf16x2

__device__ __forceinline__ float* bufptr(int id){
  switch(id){case 0:return g_x5;case 1:return g_u;case 2:return g_a1;
  case 3:return g_a2;case 4:return g_dcn;default:return g_yfin;}
}

__device__ __forceinline__ unsigned packbf(float lo,float hi){
  unsigned u; asm("cvt.rn.bf16x2.f32 %0,%1,%2;":"=r"(u):"f"(hi),"f"(lo));
  return u;
}

__device__ __forceinline__ void mma16(float* d,unsigned a0,unsigned a1,unsigned a2,
    unsigned a3,unsigned b0,unsigned b1){
  asm volatile("mma.sync.aligned.m16n8k16.row.col.f32.bf16.bf16.f32 "
    "{%0,%1,%2,%3},{%4,%5,%6,%7},{%8,%9},{%0,%1,%2,%3};"
    :"+f"(d[0]),"+f"(d[1]),"+f"(d[2]),"+f"(d[3])
    :"r"(a0),"r"(a1),"r"(a2),"r"(a3),"r"(b0),"r"(b1));
}

__global__ void k_wprep(const float* __restrict__ offw,const float* __restrict__ dcnw){
  int t=blockIdx.x*256+threadIdx.x;
  if(t<27*96*36){int k=t/3456;int rem=t-k*3456;int o=rem/36,cp=rem-o*36;
    unsigned pw=0;
    if(o<81&&cp<32){
      float f0=offw[(o*64+2*cp)*27+k],f1=offw[(o*64+2*cp+1)*27+k];
      pw=packbf(f0,f1);
    }
    g_offw_bf[t]=pw;}
  if(t<27*64*36){int k=t/2304;int rem=t-k*2304;int o=rem/36,cp=rem-o*36;
    unsigned pw=0;
    if(cp<32){
      float f0=dcnw[(o*64+2*cp)*27+k],f1=dcnw[(o*64+2*cp+1)*27+k];
      pw=packbf(f0,f1);
    }
    g_dcnw_bf[t]=pw;}
}

__global__ __launch_bounds__(256) void k_qkv(const float* __restrict__ x,const float* __restrict__ w){
  __shared__ float xs[64][65],ws[64][65];
  int b=blockIdx.x>>9,n0=(blockIdx.x&511)<<6,t=threadIdx.x;
  const float* xp=x+(b*S+n0)*64;
  for(int i=0;i<16;i++){int e=t+256*i;xs[e>>6][e&63]=xp[e];}
  int ng=t&15,og=t>>4;
  for(int pass=0;pass<3;pass++){
    __syncthreads();
    for(int i=0;i<16;i++){int e=t+256*i;ws[e>>6][e&63]=w[pass*4096+e];}
    __syncthreads();
    float acc[4][4];
    for(int i=0;i<4;i++)for(int m=0;m<4;m++)acc[i][m]=0.f;
    for(int c=0;c<64;c++){
      float xv[4],wv[4];
      #pragma unroll
      for(int m=0;m<4;m++)xv[m]=xs[ng+16*m][c];
      #pragma unroll
      for(int i=0;i<4;i++)wv[i]=ws[og+16*i][c];
      #pragma unroll
      for(int i=0;i<4;i++)
        #pragma unroll
        for(int m=0;m<4;m++)acc[i][m]+=wv[i]*xv[m];
    }
    for(int i=0;i<4;i++){int j=pass*64+og+16*i;
      for(int m=0;m<4;m++)g_qkvt[(b*192+j)*S+n0+ng+16*m]=acc[i][m];}
  }
}

__global__ void k_sumsq(){
  int id=blockIdx.x;
  int b=id>>10,j=(id>>3)&127,ch=id&7,t=threadIdx.x;
  const float* row=g_qkvt+(b*192+j)*S+ch*4096;
  float p=0.f;
  for(int i=0;i<16;i++){float v=row[t+256*i];p+=v*v;}
  __shared__ float red[256];
  red[t]=p;__syncthreads();
  for(int st=128;st>0;st>>=1){if(t<st)red[t]+=red[t+st];__syncthreads();}
  if(t==0)g_nrmp[(b*128+j)*8+ch]=red[0];
}

__global__ __launch_bounds__(256) void k_gram(){
  __shared__ float qs[16][129],ks[16][129];
  int id=blockIdx.x,chunk=id&63,h=(id>>6)&3,b=id>>8,t=threadIdx.x;
  int c=t>>4,d=t&15,nbase=chunk*512;
  const float* qrow=g_qkvt+(b*192+h*16)*S;
  const float* krow=g_qkvt+(b*192+64+h*16)*S;
  float acc=0.f;
  for(int ch=0;ch<4;ch++){
    int nb=nbase+ch*128;
    __syncthreads();
    for(int i=0;i<16;i++){int e=t+256*i;int r=e>>7,n=e&127;
      if(r<16)qs[r][n]=qrow[r*S+nb+n];else ks[r-16][n]=krow[(r-16)*S+nb+n];}
    __syncthreads();
    for(int n=0;n<128;n++)acc+=qs[c][n]*ks[d][n];
  }
  g_Gpart[((b*4+h)*64+chunk)*256+c*16+d]=acc;
}

__global__ void k_softmax(const float* __restrict__ temp){
  int b=blockIdx.x>>2,h=blockIdx.x&3,t=threadIdx.x;
  int c=t>>4,d=t&15;
  float g=0.f;
  for(int ch=0;ch<64;ch++)g+=g_Gpart[((b*4+h)*64+ch)*256+t];
  float sq=0.f,sk=0.f;
  for(int i=0;i<8;i++){
    sq+=g_nrmp[(b*128+h*16+c)*8+i];
    sk+=g_nrmp[(b*128+64+h*16+d)*8+i];
  }
  float nq=fmaxf(sqrtf(sq),1e-12f),nk=fmaxf(sqrtf(sk),1e-12f);
  float v=g/(nq*nk)*temp[h];
  float m=v;
  for(int o=8;o;o>>=1)m=fmaxf(m,__shfl_xor_sync(0xffffffffu,m,o,16));
  float e=expf(v-m),s2=e;
  for(int o=8;o;o>>=1)s2+=__shfl_xor_sync(0xffffffffu,s2,o,16);
  g_attn[(b*4+h)*256+c*16+d]=e/s2;
}

__global__ __launch_bounds__(256) void k_xca(const float* __restrict__ nw,const float* __restrict__ nb){
  __shared__ float vs[64][65],xc[64][65],at[1024],mu[64],rs[64];
  int b=blockIdx.x>>9,n0=(blockIdx.x&511)<<6,t=threadIdx.x;
  for(int i=0;i<16;i++){int e=t+256*i;int r=e>>6,n=e&63;
    vs[r][n]=g_qkvt[(b*192+128+r)*S+n0+n];}
  for(int i=0;i<4;i++)at[t+256*i]=g_attn[b*1024+t+256*i];
  __syncthreads();
  int sl=t&63,og=t>>6;
  for(int i=0;i<16;i++){
    float a=0.f;
    const float* ar=at+og*256+i*16;
    #pragma unroll
    for(int d=0;d<16;d++)a+=ar[d]*vs[og*16+d][sl];
    xc[og*16+i][sl]=a;
  }
  __syncthreads();
  if(t<64){
    float s1=0.f;
    for(int c2=0;c2<64;c2++)s1+=xc[c2][t];
    float m=s1*(1.f/64.f),sq=0.f;
    for(int c2=0;c2<64;c2++){float d2=xc[c2][t]-m;sq+=d2*d2;}
    mu[t]=m;rs[t]=rsqrtf(sq*(1.f/64.f)+1e-5f);
  }
  __syncthreads();
  for(int i=0;i<16;i++){int c=og*16+i;
    g_x5[(b*64+c)*S+n0+sl]=(xc[c][sl]-mu[sl])*rs[sl]*nw[c]+nb[c];}
}

template<int MODE>
__global__ __launch_bounds__(256) void k_pw(int inid,int auxid,int outid,
    const float* __restrict__ w,const float* __restrict__ bias){
  __shared__ float xs[64][65],ws2[64][65];
  const float* in=bufptr(inid);const float* aux=bufptr(auxid);float* out=bufptr(outid);
  int b=blockIdx.x>>9,s0=(blockIdx.x&511)<<6,t=threadIdx.x;
  for(int i=0;i<16;i++){int e=t+256*i;int c=e>>6,s=e&63;
    xs[c][s]=in[(b*64+c)*S+s0+s];ws2[c][s]=w[e];}
  __syncthreads();
  int sg=t&15,og=t>>4;
  float acc[4][4];
  for(int i=0;i<4;i++)for(int m=0;m<4;m++)acc[i][m]=0.f;
  for(int c=0;c<64;c++){
    float xv[4],wv[4];
    #pragma unroll
    for(int m=0;m<4;m++)xv[m]=xs[c][sg+16*m];
    #pragma unroll
    for(int i=0;i<4;i++)wv[i]=ws2[og+16*i][c];
    #pragma unroll
    for(int i=0;i<4;i++)
      #pragma unroll
      for(int m=0;m<4;m++)acc[i][m]+=wv[i]*xv[m];
  }
  for(int i=0;i<4;i++){
    int o=og+16*i;float bv=bias[o];
    for(int m=0;m<4;m++){
      int idx=(b*64+o)*S+s0+sg+16*m;
      float v=acc[i][m]+bv;
      if(MODE==1)v=0.5f*v*(1.f+erff(v*0.70710678118654752f));
      if(MODE==2)v*=aux[idx];
      if(MODE==3)v+=aux[idx];
      out[idx]=v;
    }
  }
}

__global__ __launch_bounds__(256) void k_dw5(int inid,int outid,
    const float* __restrict__ wt,const float* __restrict__ bias){
  __shared__ float pl[5][32][37];__shared__ float wsm[125];
  const float* in=bufptr(inid);float* out=bufptr(outid);
  int bc=blockIdx.x>>5,z=blockIdx.x&31,c=bc&63,t=threadIdx.x;
  if(t<125)wsm[t]=wt[c*125+t];
  const float* base=in+bc*S;
  for(int e=t;e<5*32*37;e+=256){
    int p=e/1184,rem=e-p*1184;
    int y=rem/37,xp=rem-y*37;
    int zz=z+p-2,gx=xp-2;
    float v=0.f;
    if((unsigned)zz<32u&&(unsigned)gx<32u)v=base[zz*1024+y*32+gx];
    pl[p][y][xp]=v;
  }
  __syncthreads();
  int x=t&31,ty=t>>5;
  float bv=bias[c];
  float acc[4]={bv,bv,bv,bv};
  for(int tz=0;tz<5;tz++)
    for(int qy=0;qy<5;qy++){
      float w5[5];
      #pragma unroll
      for(int qx=0;qx<5;qx++)w5[qx]=wsm[(tz*5+qy)*5+qx];
      int yb=qy-2;
      #pragma unroll
      for(int m=0;m<4;m++){
        int yy=ty+8*m+yb;
        if((unsigned)yy<32u){
          #pragma unroll
          for(int qx=0;qx<5;qx++)acc[m]+=w5[qx]*pl[tz][yy][x+qx];
        }
      }
    }
  #pragma unroll
  for(int m=0;m<4;m++)
    out[bc*S+z*1024+(ty+8*m)*32+x]=acc[m];
}

__global__ __launch_bounds__(256) void k_dw7(int inid,int outid,
    const float* __restrict__ wt,const float* __restrict__ bias){
  __shared__ float pl[7][32][52];__shared__ float wsm[343];
  const float* in=bufptr(inid);float* out=bufptr(outid);
  int bc=blockIdx.x>>5,z=blockIdx.x&31,c=bc&63,t=threadIdx.x;
  for(int i=t;i<343;i+=256)wsm[i]=wt[c*343+i];
  const float* base=in+bc*S;
  for(int e=t;e<7*32*52;e+=256){
    int p=e/1664,rem=e-p*1664;
    int y=rem/52,xp=rem-y*52;
    int zz=z+3*p-9,gx=xp-9;
    float v=0.f;
    if((unsigned)zz<32u&&(unsigned)gx<32u)v=base[zz*1024+y*32+gx];
    pl[p][y][xp]=v;
  }
  __syncthreads();
  int x=t&31,ty=t>>5;
  float bv=bias[c];
  float acc[4]={bv,bv,bv,bv};
  for(int tz=0;tz<7;tz++)
    for(int qy=0;qy<7;qy++){
      float w7[7];
      #pragma unroll
      for(int qx=0;qx<7;qx++)w7[qx]=wsm[(tz*7+qy)*7+qx];
      int yb=3*qy-9;
      #pragma unroll
      for(int m=0;m<4;m++){
        int yy=ty+8*m+yb;
        if((unsigned)yy<32u){
          #pragma unroll
          for(int qx=0;qx<7;qx++)acc[m]+=w7[qx]*pl[tz][yy][x+3*qx];
        }
      }
    }
  #pragma unroll
  for(int m=0;m<4;m++)
    out[bc*S+z*1024+(ty+8*m)*32+x]=acc[m];
}

// tile-transpose a2 [c][s] -> a2t [s][c]
__global__ __launch_bounds__(256) void k_tr(){
  __shared__ float ts[64][65];
  int b=blockIdx.x>>9,s0=(blockIdx.x&511)<<6,t=threadIdx.x;
  for(int i=0;i<16;i++){int e=t+256*i;int c=e>>6,s=e&63;
    ts[c][s]=g_a2[(b*64+c)*S+s0+s];}
  __syncthreads();
  for(int i=0;i<16;i++){int e=t+256*i;int s=e>>6,c=e&63;
    g_a2t[(b*S+s0+s)*64+c]=ts[c][s];}
}

// offset conv via bf16 MMA: M=64 spatial, N=96 outputs, K=27*64
__global__ __launch_bounds__(256) void k_off(const float* __restrict__ offb){
  __shared__ unsigned rows[2][32][40];   // [r][cpair][x pad40] bf16x2
  __shared__ unsigned wsm[96*36];        // [o][cpair pad36] bf16x2
  int blk=blockIdx.x;
  int b=blk>>9,z=(blk>>4)&31,y0=(blk&15)<<1,t=threadIdx.x;
  int w=t>>5,l=t&31;
  int mt=w>>1,nh=w&1;
  int lr=l>>2,lc=l&3;
  float acc[6][4];
  for(int j=0;j<6;j++)for(int q=0;q<4;q++)acc[j][q]=0.f;
  const float* ab=g_a2+b*64*S;
  int sA_=mt*16+lr, sB_=sA_+8;
  int r0=sA_>>5,xa=sA_&31;
  int r1=sB_>>5,xb=sB_&31;
  for(int tz=0;tz<3;tz++){
    int zz=z+tz-1;bool zok=(unsigned)zz<32u;
    for(int ty=0;ty<3;ty++){
      __syncthreads();
      for(int i=0;i<9;i++){
        int e=t+256*i;
        if(e<2176){
          int r=e/1088,rem=e-r*1088;
          int cp=rem/34,xi=rem-cp*34;
          int yy=y0+ty-1+r,gx=xi-1;
          float v0=0.f,v1=0.f;
          if(zok&&(unsigned)yy<32u&&(unsigned)gx<32u){
            int sp=zz*1024+yy*32+gx;
            v0=ab[(2*cp)*S+sp];v1=ab[(2*cp+1)*S+sp];
          }
          rows[r][cp][xi]=packbf(v0,v1);
        }
      }
      for(int tx=0;tx<3;tx++){
        int k=(tz*3+ty)*3+tx;
        __syncthreads();
        for(int i=0;i<14;i++){int e=t+256*i;if(e<3456)wsm[e]=g_offw_bf[k*3456+e];}
        __syncthreads();
        #pragma unroll
        for(int kc=0;kc<4;kc++){
          unsigned a0=rows[r0][kc*8+lc][xa+tx];
          unsigned a1=rows[r1][kc*8+lc][xb+tx];
          unsigned a2v=rows[r0][kc*8+lc+4][xa+tx];
          unsigned a3=rows[r1][kc*8+lc+4][xb+tx];
          #pragma unroll
          for(int j=0;j<6;j++){
            int o=(nh*6+j)*8+lr;
            unsigned b0=wsm[o*36+kc*8+lc];
            unsigned b1=wsm[o*36+kc*8+lc+4];
            mma16(acc[j],a0,a1,a2v,a3,b0,b1);
          }
        }
      }
    }
  }
  int spA=z*1024+(y0+r0)*32+xa;
  int spB=z*1024+(y0+r1)*32+xb;
  #pragma unroll
  for(int j=0;j<6;j++){
    int ob=(nh*6+j)*8;
    #pragma unroll
    for(int q=0;q<2;q++){
      int o=ob+2*lc+q;
      if(o<81){
        float bv=offb[o];
        g_off[(b*81+o)*S+spA]=acc[j][q]+bv;
        g_off[(b*81+o)*S+spB]=acc[j][q+2]+bv;
      }
    }
  }
}

// deformable conv: coalesced gather + bf16 m16n8k16 MMA
__global__ __launch_bounds__(256) void k_dcn(const float* __restrict__ dcnb){
  extern __shared__ unsigned dynu[];
  unsigned* samp=dynu;                 // [128][36] bf16x2 words
  unsigned* wsm=dynu+128*36;           // [64][36]  bf16x2 words
  float* cw=(float*)(wsm+64*36);       // [8][128]
  int* ci=(int*)(cw+1024);             // [8][128]
  int b=blockIdx.x>>8,s0=(blockIdx.x&255)<<7,t=threadIdx.x;
  int w=t>>5,l=t&31,mt=w>>1,nh=w&1,lr=l>>2,lc=l&3;
  float acc[8][4];
  for(int j=0;j<8;j++)for(int q=0;q<4;q++)acc[j][q]=0.f;
  const float* at=g_a2t+(size_t)b*64*S;
  for(int k=0;k<27;k++){
    __syncthreads();
    if(t<128){
      int s=s0+t;
      int z=s>>10,y=(s>>5)&31,x=s&31;
      int kz=k/9,ky=(k/3)%3,kx=k%3;
      float pz=(float)(z+kz-1)+g_off[(b*81+3*k+0)*S+s];
      float py=(float)(y+ky-1)+g_off[(b*81+3*k+1)*S+s];
      float px=(float)(x+kx-1)+g_off[(b*81+3*k+2)*S+s];
      float fz=floorf(pz),fy=floorf(py),fx=floorf(px);
      float wz=pz-fz,wy=py-fy,wx=px-fx;
      int z0=(int)fz,y0=(int)fy,x0=(int)fx;
      #pragma unroll
      for(int cn=0;cn<8;cn++){
        int dz=cn>>2,dy=(cn>>1)&1,dx=cn&1;
        int iz=z0+dz,iy=y0+dy,ix=x0+dx;
        float wv=(dz?wz:1.f-wz)*(dy?wy:1.f-wy)*(dx?wx:1.f-wx);
        bool ok=(unsigned)iz<32u&&(unsigned)iy<32u&&(unsigned)ix<32u;
        int czi=min(max(iz,0),31),cyi=min(max(iy,0),31),cxi=min(max(ix,0),31);
        cw[cn*128+t]=ok?wv:0.f;
        ci[cn*128+t]=(czi*32+cyi)*32+cxi;
      }
    }
    for(int i=0;i<9;i++){int e=t+256*i;if(e<2304)wsm[e]=g_dcnw_bf[k*2304+e];}
    __syncthreads();
    #pragma unroll
    for(int i=0;i<8;i++){
      int e=t+256*i;int sp=e>>4,q=(e&15)<<2;
      float ax=0.f,ay=0.f,az=0.f,aw=0.f;
      #pragma unroll
      for(int cn=0;cn<8;cn++){
        float wv=cw[cn*128+sp];
        const float4 v4=*(const float4*)(at+(size_t)ci[cn*128+sp]*64+q);
        ax+=wv*v4.x;ay+=wv*v4.y;az+=wv*v4.z;aw+=wv*v4.w;
      }
      unsigned* sw=samp+sp*36+(q>>1);
      sw[0]=packbf(ax,ay);
      sw[1]=packbf(az,aw);
    }
    __syncthreads();
    int oA=mt*16+lr;
    #pragma unroll
    for(int kc=0;kc<4;kc++){
      unsigned a0=wsm[(oA  )*36+kc*8+lc];
      unsigned a1=wsm[(oA+8)*36+kc*8+lc];
      unsigned a2v=wsm[(oA  )*36+kc*8+lc+4];
      unsigned a3=wsm[(oA+8)*36+kc*8+lc+4];
      #pragma unroll
      for(int j=0;j<8;j++){
        int spc=(nh*8+j)*8+lr;
        unsigned b0=samp[spc*36+kc*8+lc];
        unsigned b1=samp[spc*36+kc*8+lc+4];
        mma16(acc[j],a0,a1,a2v,a3,b0,b1);
      }
    }
  }
  int oA=mt*16+lr;
  float bv0=dcnb[oA],bv1=dcnb[oA+8];
  #pragma unroll
  for(int j=0;j<8;j++){
    int spb=(nh*8+j)*8;
    #pragma unroll
    for(int q=0;q<2;q++){
      int spc=spb+2*lc+q;
      g_dcn[(b*64+oA)*S+s0+spc]=acc[j][q]+bv0;
      g_dcn[(b*64+oA+8)*S+s0+spc]=acc[j][q+2]+bv1;
    }
  }
}

__global__ __launch_bounds__(256) void k_final(const float* __restrict__ n2w,
    const float* __restrict__ n2b,const float* __restrict__ ow,
    const float* __restrict__ ob,float* __restrict__ out){
  __shared__ float Msm[64][65],wsm[64][65],mu[64],rs[64];
  int b=blockIdx.x>>9,g=blockIdx.x&511,t=threadIdx.x;
  for(int i=0;i<16;i++){int e=t+256*i;int r=e>>6,p=e&63;
    Msm[r][p]=g_yfin[(b*64+r)*S+g+(p<<9)];
    wsm[r][p]=ow[e];}
  __syncthreads();
  if(t<64){
    float s1=0.f;
    for(int p=0;p<64;p++)s1+=Msm[t][p];
    float m=s1*(1.f/64.f),sq=0.f;
    for(int p=0;p<64;p++){float d=Msm[t][p]-m;sq+=d*d;}
    mu[t]=m;rs[t]=rsqrtf(sq*(1.f/64.f)+1e-5f);
  }
  __syncthreads();
  for(int i=0;i<16;i++){int e=t+256*i;int r=e>>6,p=e&63;
    Msm[r][p]=(Msm[r][p]-mu[r])*rs[r]*n2w[p]+n2b[p];}
  __syncthreads();
  int og=t&15,sg=t>>4;
  float acc[4][4];
  for(int m=0;m<4;m++)for(int i=0;i<4;i++)acc[m][i]=0.f;
  for(int p=0;p<64;p++){
    float xv[4],wv[4];
    #pragma unroll
    for(int m=0;m<4;m++)xv[m]=Msm[sg+16*m][p];
    #pragma unroll
    for(int i=0;i<4;i++)wv[i]=wsm[og+16*i][p];
    #pragma unroll
    for(int m=0;m<4;m++)
      #pragma unroll
      for(int i=0;i<4;i++)acc[m][i]+=xv[m]*wv[i];
  }
  for(int m=0;m<4;m++){
    int q=(g<<6)+sg+16*m;
    for(int i=0;i<4;i++){
      int o=og+16*i;
      out[(b*S+q)*64+o]=acc[m][i]+ob[o];
    }
  }
}

extern "C" void kernel_launch(void* const* d_in,const int* in_sizes,int n_in,
                              void* d_out,int out_size){
  const float* x   =(const float*)d_in[0];
  const float* temp=(const float*)d_in[1];
  const float* qkvw=(const float*)d_in[2];
  const float* nw  =(const float*)d_in[3];
  const float* nb  =(const float*)d_in[4];
  const float* p1w =(const float*)d_in[5];
  const float* p1b =(const float*)d_in[6];
  const float* c0w =(const float*)d_in[7];
  const float* c0b =(const float*)d_in[8];
  const float* cspw=(const float*)d_in[9];
  const float* cspb=(const float*)d_in[10];
  const float* offw=(const float*)d_in[11];
  const float* offb=(const float*)d_in[12];
  const float* dcnw=(const float*)d_in[13];
  const float* dcnb=(const float*)d_in[14];
  const float* c1w =(const float*)d_in[15];
  const float* c1b =(const float*)d_in[16];
  const float* p2w =(const float*)d_in[17];
  const float* p2b =(const float*)d_in[18];
  const float* n2w =(const float*)d_in[19];
  const float* n2b =(const float*)d_in[20];
  const float* ow  =(const float*)d_in[21];
  const float* ob  =(const float*)d_in[22];
  float* out=(float*)d_out;

  int dcn_smem=(128*36+64*36+1024+1024)*4;  // 35840 B
  cudaFuncSetAttribute(k_dcn,cudaFuncAttributeMaxDynamicSharedMemorySize,dcn_smem);

  k_wprep<<<648,256>>>(offw,dcnw);
  k_qkv<<<1024,256>>>(x,qkvw);
  k_sumsq<<<2048,256>>>();
  k_gram<<<512,256>>>();
  k_softmax<<<8,256>>>(temp);
  k_xca<<<1024,256>>>(nw,nb);
  k_pw<1><<<1024,256>>>(0,0,1,p1w,p1b);   // u = gelu(proj1(x5))
  k_dw5<<<4096,256>>>(1,2,c0w,c0b);       // a1 = dw5(u)
  k_dw7<<<4096,256>>>(2,3,cspw,cspb);     // a2 = dw7(a1)
  k_tr<<<1024,256>>>();                   // a2 -> a2t (spatial-major)
  k_off<<<1024,256>>>(offb);              // offsets from a2 (bf16 MMA)
  k_dcn<<<512,256,dcn_smem>>>(dcnb);      // deformable conv (bf16 MMA)
  k_pw<2><<<1024,256>>>(4,1,2,c1w,c1b);   // a1 = (conv1(dcn)+b)*u
  k_pw<3><<<1024,256>>>(2,0,5,p2w,p2b);   // yfin = proj2(a1)+x5
  k_final<<<1024,256>>>(n2w,n2b,ow,ob,out);
}

// round 17
// speedup vs baseline: 2.4358x; 1.1682x over previous
#include <cuda_runtime.h>
#include <math.h>

#define S 32768

static __device__ float g_qkvt[2*192*S];
static __device__ float g_nrmp[2*128*8];
static __device__ float g_Gpart[2*4*64*256];
static __device__ float g_attn[2*4*256];
static __device__ float g_x5[2*64*S];
static __device__ float g_u[2*64*S];
static __device__ float g_a1[2*64*S];
static __device__ float g_a2[2*64*S];
static __device__ unsigned g_a2bf[2*S*32];      // spatial-major bf16x2 [b][s][cpair]
static __device__ float g_off[2*81*S];
static __device__ float g_dcn[2*64*S];
static __device__ float g_yfin[2*64*S];
static __device__ unsigned g_offw_bf[27*96*36]; // [tap][o pad96][cpair pad36] bf16x2
static __device__ unsigned g_dcnw_bf[27*64*36]; // [tap][o][cpair pad36] bf16x2

__device__ __forceinline__ float* bufptr(int id){
  switch(id){case 0:return g_x5;case 1:return g_u;case 2:return g_a1;
  case 3:return g_a2;case 4:return g_dcn;default:return g_yfin;}
}

__device__ __forceinline__ unsigned packbf(float lo,float hi){
  unsigned u; asm("cvt.rn.bf16x2.f32 %0,%1,%2;":"=r"(u):"f"(hi),"f"(lo));
  return u;
}

__device__ __forceinline__ unsigned bffma(unsigned a,unsigned b,unsigned c){
  unsigned d; asm("fma.rn.bf16x2 %0,%1,%2,%3;":"=r"(d):"r"(a),"r"(b),"r"(c));
  return d;
}

__device__ __forceinline__ void mma16(float* d,unsigned a0,unsigned a1,unsigned a2,
    unsigned a3,unsigned b0,unsigned b1){
  asm volatile("mma.sync.aligned.m16n8k16.row.col.f32.bf16.bf16.f32 "
    "{%0,%1,%2,%3},{%4,%5,%6,%7},{%8,%9},{%0,%1,%2,%3};"
    :"+f"(d[0]),"+f"(d[1]),"+f"(d[2]),"+f"(d[3])
    :"r"(a0),"r"(a1),"r"(a2),"r"(a3),"r"(b0),"r"(b1));
}

__global__ void k_wprep(const float* __restrict__ offw,const float* __restrict__ dcnw){
  int t=blockIdx.x*256+threadIdx.x;
  if(t<27*96*36){int k=t/3456;int rem=t-k*3456;int o=rem/36,cp=rem-o*36;
    unsigned pw=0;
    if(o<81&&cp<32){
      float f0=offw[(o*64+2*cp)*27+k],f1=offw[(o*64+2*cp+1)*27+k];
      pw=packbf(f0,f1);
    }
    g_offw_bf[t]=pw;}
  if(t<27*64*36){int k=t/2304;int rem=t-k*2304;int o=rem/36,cp=rem-o*36;
    unsigned pw=0;
    if(cp<32){
      float f0=dcnw[(o*64+2*cp)*27+k],f1=dcnw[(o*64+2*cp+1)*27+k];
      pw=packbf(f0,f1);
    }
    g_dcnw_bf[t]=pw;}
}

__global__ __launch_bounds__(256) void k_qkv(const float* __restrict__ x,const float* __restrict__ w){
  __shared__ float xs[64][65],ws[64][65];
  int b=blockIdx.x>>9,n0=(blockIdx.x&511)<<6,t=threadIdx.x;
  const float* xp=x+(b*S+n0)*64;
  for(int i=0;i<16;i++){int e=t+256*i;xs[e>>6][e&63]=xp[e];}
  int ng=t&15,og=t>>4;
  for(int pass=0;pass<3;pass++){
    __syncthreads();
    for(int i=0;i<16;i++){int e=t+256*i;ws[e>>6][e&63]=w[pass*4096+e];}
    __syncthreads();
    float acc[4][4];
    for(int i=0;i<4;i++)for(int m=0;m<4;m++)acc[i][m]=0.f;
    for(int c=0;c<64;c++){
      float xv[4],wv[4];
      #pragma unroll
      for(int m=0;m<4;m++)xv[m]=xs[ng+16*m][c];
      #pragma unroll
      for(int i=0;i<4;i++)wv[i]=ws[og+16*i][c];
      #pragma unroll
      for(int i=0;i<4;i++)
        #pragma unroll
        for(int m=0;m<4;m++)acc[i][m]+=wv[i]*xv[m];
    }
    for(int i=0;i<4;i++){int j=pass*64+og+16*i;
      for(int m=0;m<4;m++)g_qkvt[(b*192+j)*S+n0+ng+16*m]=acc[i][m];}
  }
}

__global__ void k_sumsq(){
  int id=blockIdx.x;
  int b=id>>10,j=(id>>3)&127,ch=id&7,t=threadIdx.x;
  const float* row=g_qkvt+(b*192+j)*S+ch*4096;
  float p=0.f;
  for(int i=0;i<16;i++){float v=row[t+256*i];p+=v*v;}
  __shared__ float red[256];
  red[t]=p;__syncthreads();
  for(int st=128;st>0;st>>=1){if(t<st)red[t]+=red[t+st];__syncthreads();}
  if(t==0)g_nrmp[(b*128+j)*8+ch]=red[0];
}

__global__ __launch_bounds__(256) void k_gram(){
  __shared__ float qs[16][129],ks[16][129];
  int id=blockIdx.x,chunk=id&63,h=(id>>6)&3,b=id>>8,t=threadIdx.x;
  int c=t>>4,d=t&15,nbase=chunk*512;
  const float* qrow=g_qkvt+(b*192+h*16)*S;
  const float* krow=g_qkvt+(b*192+64+h*16)*S;
  float acc=0.f;
  for(int ch=0;ch<4;ch++){
    int nb=nbase+ch*128;
    __syncthreads();
    for(int i=0;i<16;i++){int e=t+256*i;int r=e>>7,n=e&127;
      if(r<16)qs[r][n]=qrow[r*S+nb+n];else ks[r-16][n]=krow[(r-16)*S+nb+n];}
    __syncthreads();
    for(int n=0;n<128;n++)acc+=qs[c][n]*ks[d][n];
  }
  g_Gpart[((b*4+h)*64+chunk)*256+c*16+d]=acc;
}

__global__ void k_softmax(const float* __restrict__ temp){
  int b=blockIdx.x>>2,h=blockIdx.x&3,t=threadIdx.x;
  int c=t>>4,d=t&15;
  float g=0.f;
  for(int ch=0;ch<64;ch++)g+=g_Gpart[((b*4+h)*64+ch)*256+t];
  float sq=0.f,sk=0.f;
  for(int i=0;i<8;i++){
    sq+=g_nrmp[(b*128+h*16+c)*8+i];
    sk+=g_nrmp[(b*128+64+h*16+d)*8+i];
  }
  float nq=fmaxf(sqrtf(sq),1e-12f),nk=fmaxf(sqrtf(sk),1e-12f);
  float v=g/(nq*nk)*temp[h];
  float m=v;
  for(int o=8;o;o>>=1)m=fmaxf(m,__shfl_xor_sync(0xffffffffu,m,o,16));
  float e=expf(v-m),s2=e;
  for(int o=8;o;o>>=1)s2+=__shfl_xor_sync(0xffffffffu,s2,o,16);
  g_attn[(b*4+h)*256+c*16+d]=e/s2;
}

__global__ __launch_bounds__(256) void k_xca(const float* __restrict__ nw,const float* __restrict__ nb){
  __shared__ float vs[64][65],xc[64][65],at[1024],mu[64],rs[64];
  int b=blockIdx.x>>9,n0=(blockIdx.x&511)<<6,t=threadIdx.x;
  for(int i=0;i<16;i++){int e=t+256*i;int r=e>>6,n=e&63;
    vs[r][n]=g_qkvt[(b*192+128+r)*S+n0+n];}
  for(int i=0;i<4;i++)at[t+256*i]=g_attn[b*1024+t+256*i];
  __syncthreads();
  int sl=t&63,og=t>>6;
  for(int i=0;i<16;i++){
    float a=0.f;
    const float* ar=at+og*256+i*16;
    #pragma unroll
    for(int d=0;d<16;d++)a+=ar[d]*vs[og*16+d][sl];
    xc[og*16+i][sl]=a;
  }
  __syncthreads();
  if(t<64){
    float s1=0.f;
    for(int c2=0;c2<64;c2++)s1+=xc[c2][t];
    float m=s1*(1.f/64.f),sq=0.f;
    for(int c2=0;c2<64;c2++){float d2=xc[c2][t]-m;sq+=d2*d2;}
    mu[t]=m;rs[t]=rsqrtf(sq*(1.f/64.f)+1e-5f);
  }
  __syncthreads();
  for(int i=0;i<16;i++){int c=og*16+i;
    g_x5[(b*64+c)*S+n0+sl]=(xc[c][sl]-mu[sl])*rs[sl]*nw[c]+nb[c];}
}

// pointwise GEMM via bf16 MMA: 128 sp per block
template<int MODE>
__global__ __launch_bounds__(256) void k_pw(int inid,int auxid,int outid,
    const float* __restrict__ w,const float* __restrict__ bias){
  __shared__ unsigned samp[128*36];   // [sp][cpair pad36]
  __shared__ unsigned wsmb[64*36];    // [o][cpair pad36]
  const float* in=bufptr(inid);const float* aux=bufptr(auxid);float* out=bufptr(outid);
  int b=blockIdx.x>>8,s0=(blockIdx.x&255)<<7,t=threadIdx.x;
  int wd=t>>5,l=t&31,mt=wd>>1,nh=wd&1,lr=l>>2,lc=l&3;
  for(int i=0;i<8;i++){int e=t+256*i;int o=e>>5,cp=e&31;
    wsmb[o*36+cp]=packbf(w[o*64+2*cp],w[o*64+2*cp+1]);}
  for(int i=0;i<16;i++){int e=t+256*i;int cp=e>>7,sp=e&127;
    samp[sp*36+cp]=packbf(in[(b*64+2*cp)*S+s0+sp],in[(b*64+2*cp+1)*S+s0+sp]);}
  __syncthreads();
  float acc[8][4];
  for(int j=0;j<8;j++)for(int q=0;q<4;q++)acc[j][q]=0.f;
  int oA=mt*16+lr;
  #pragma unroll
  for(int kc=0;kc<4;kc++){
    unsigned a0=wsmb[(oA  )*36+kc*8+lc];
    unsigned a1=wsmb[(oA+8)*36+kc*8+lc];
    unsigned a2v=wsmb[(oA  )*36+kc*8+lc+4];
    unsigned a3=wsmb[(oA+8)*36+kc*8+lc+4];
    #pragma unroll
    for(int j=0;j<8;j++){
      int spc=(nh*8+j)*8+lr;
      unsigned b0=samp[spc*36+kc*8+lc];
      unsigned b1=samp[spc*36+kc*8+lc+4];
      mma16(acc[j],a0,a1,a2v,a3,b0,b1);
    }
  }
  float bv0=bias[oA],bv1=bias[oA+8];
  #pragma unroll
  for(int j=0;j<8;j++){
    int spb=(nh*8+j)*8;
    #pragma unroll
    for(int q=0;q<2;q++){
      int spc=spb+2*lc+q;
      int i0=(b*64+oA)*S+s0+spc;
      int i1=(b*64+oA+8)*S+s0+spc;
      float v0=acc[j][q]+bv0,v1=acc[j][q+2]+bv1;
      if(MODE==1){
        v0=0.5f*v0*(1.f+erff(v0*0.70710678118654752f));
        v1=0.5f*v1*(1.f+erff(v1*0.70710678118654752f));
      }
      if(MODE==2){v0*=aux[i0];v1*=aux[i1];}
      if(MODE==3){v0+=aux[i0];v1+=aux[i1];}
      out[i0]=v0;out[i1]=v1;
    }
  }
}

__global__ __launch_bounds__(256) void k_dw5(int inid,int outid,
    const float* __restrict__ wt,const float* __restrict__ bias){
  __shared__ float pl[5][32][37];__shared__ float wsm[125];
  const float* in=bufptr(inid);float* out=bufptr(outid);
  int bc=blockIdx.x>>5,z=blockIdx.x&31,c=bc&63,t=threadIdx.x;
  if(t<125)wsm[t]=wt[c*125+t];
  const float* base=in+bc*S;
  for(int e=t;e<5*32*37;e+=256){
    int p=e/1184,rem=e-p*1184;
    int y=rem/37,xp=rem-y*37;
    int zz=z+p-2,gx=xp-2;
    float v=0.f;
    if((unsigned)zz<32u&&(unsigned)gx<32u)v=base[zz*1024+y*32+gx];
    pl[p][y][xp]=v;
  }
  __syncthreads();
  int x=t&31,ty=t>>5;
  float bv=bias[c];
  float acc[4]={bv,bv,bv,bv};
  for(int tz=0;tz<5;tz++)
    for(int qy=0;qy<5;qy++){
      float w5[5];
      #pragma unroll
      for(int qx=0;qx<5;qx++)w5[qx]=wsm[(tz*5+qy)*5+qx];
      int yb=qy-2;
      #pragma unroll
      for(int m=0;m<4;m++){
        int yy=ty+8*m+yb;
        if((unsigned)yy<32u){
          #pragma unroll
          for(int qx=0;qx<5;qx++)acc[m]+=w5[qx]*pl[tz][yy][x+qx];
        }
      }
    }
  #pragma unroll
  for(int m=0;m<4;m++)
    out[bc*S+z*1024+(ty+8*m)*32+x]=acc[m];
}

__global__ __launch_bounds__(256) void k_dw7(int inid,int outid,
    const float* __restrict__ wt,const float* __restrict__ bias){
  __shared__ float pl[7][32][52];__shared__ float wsm[343];
  const float* in=bufptr(inid);float* out=bufptr(outid);
  int bc=blockIdx.x>>5,z=blockIdx.x&31,c=bc&63,t=threadIdx.x;
  for(int i=t;i<343;i+=256)wsm[i]=wt[c*343+i];
  const float* base=in+bc*S;
  for(int e=t;e<7*32*52;e+=256){
    int p=e/1664,rem=e-p*1664;
    int y=rem/52,xp=rem-y*52;
    int zz=z+3*p-9,gx=xp-9;
    float v=0.f;
    if((unsigned)zz<32u&&(unsigned)gx<32u)v=base[zz*1024+y*32+gx];
    pl[p][y][xp]=v;
  }
  __syncthreads();
  int x=t&31,ty=t>>5;
  float bv=bias[c];
  float acc[4]={bv,bv,bv,bv};
  for(int tz=0;tz<7;tz++)
    for(int qy=0;qy<7;qy++){
      float w7[7];
      #pragma unroll
      for(int qx=0;qx<7;qx++)w7[qx]=wsm[(tz*7+qy)*7+qx];
      int yb=3*qy-9;
      #pragma unroll
      for(int m=0;m<4;m++){
        int yy=ty+8*m+yb;
        if((unsigned)yy<32u){
          #pragma unroll
          for(int qx=0;qx<7;qx++)acc[m]+=w7[qx]*pl[tz][yy][x+3*qx];
        }
      }
    }
  #pragma unroll
  for(int m=0;m<4;m++)
    out[bc*S+z*1024+(ty+8*m)*32+x]=acc[m];
}

// tile-transpose a2 [c][s] -> bf16x2 a2bf [s][cpair]
__global__ __launch_bounds__(256) void k_tr(){
  __shared__ float ts[64][65];
  int b=blockIdx.x>>9,s0=(blockIdx.x&511)<<6,t=threadIdx.x;
  for(int i=0;i<16;i++){int e=t+256*i;int c=e>>6,s=e&63;
    ts[c][s]=g_a2[(b*64+c)*S+s0+s];}
  __syncthreads();
  for(int i=0;i<8;i++){int e=t+256*i;int s=e>>5,cp=e&31;
    g_a2bf[(b*S+s0+s)*32+cp]=packbf(ts[2*cp][s],ts[2*cp+1][s]);}
}

// offset conv via bf16 MMA: M=64 spatial, N=96 outputs, K=27*64
__global__ __launch_bounds__(256) void k_off(const float* __restrict__ offb){
  __shared__ unsigned rows[2][32][40];   // [r][cpair][x pad40] bf16x2
  __shared__ unsigned wsm[96*36];        // [o][cpair pad36] bf16x2
  int blk=blockIdx.x;
  int b=blk>>9,z=(blk>>4)&31,y0=(blk&15)<<1,t=threadIdx.x;
  int w=t>>5,l=t&31;
  int mt=w>>1,nh=w&1;
  int lr=l>>2,lc=l&3;
  float acc[6][4];
  for(int j=0;j<6;j++)for(int q=0;q<4;q++)acc[j][q]=0.f;
  const float* ab=g_a2+b*64*S;
  int sA_=mt*16+lr, sB_=sA_+8;
  int r0=sA_>>5,xa=sA_&31;
  int r1=sB_>>5,xb=sB_&31;
  for(int tz=0;tz<3;tz++){
    int zz=z+tz-1;bool zok=(unsigned)zz<32u;
    for(int ty=0;ty<3;ty++){
      __syncthreads();
      for(int i=0;i<9;i++){
        int e=t+256*i;
        if(e<2176){
          int r=e/1088,rem=e-r*1088;
          int cp=rem/34,xi=rem-cp*34;
          int yy=y0+ty-1+r,gx=xi-1;
          float v0=0.f,v1=0.f;
          if(zok&&(unsigned)yy<32u&&(unsigned)gx<32u){
            int sp=zz*1024+yy*32+gx;
            v0=ab[(2*cp)*S+sp];v1=ab[(2*cp+1)*S+sp];
          }
          rows[r][cp][xi]=packbf(v0,v1);
        }
      }
      for(int tx=0;tx<3;tx++){
        int k=(tz*3+ty)*3+tx;
        __syncthreads();
        for(int i=0;i<14;i++){int e=t+256*i;if(e<3456)wsm[e]=g_offw_bf[k*3456+e];}
        __syncthreads();
        #pragma unroll
        for(int kc=0;kc<4;kc++){
          unsigned a0=rows[r0][kc*8+lc][xa+tx];
          unsigned a1=rows[r1][kc*8+lc][xb+tx];
          unsigned a2v=rows[r0][kc*8+lc+4][xa+tx];
          unsigned a3=rows[r1][kc*8+lc+4][xb+tx];
          #pragma unroll
          for(int j=0;j<6;j++){
            int o=(nh*6+j)*8+lr;
            unsigned b0=wsm[o*36+kc*8+lc];
            unsigned b1=wsm[o*36+kc*8+lc+4];
            mma16(acc[j],a0,a1,a2v,a3,b0,b1);
          }
        }
      }
    }
  }
  int spA=z*1024+(y0+r0)*32+xa;
  int spB=z*1024+(y0+r1)*32+xb;
  #pragma unroll
  for(int j=0;j<6;j++){
    int ob=(nh*6+j)*8;
    #pragma unroll
    for(int q=0;q<2;q++){
      int o=ob+2*lc+q;
      if(o<81){
        float bv=offb[o];
        g_off[(b*81+o)*S+spA]=acc[j][q]+bv;
        g_off[(b*81+o)*S+spB]=acc[j][q+2]+bv;
      }
    }
  }
}

// deformable conv: bf16 gather + bf16 m16n8k16 MMA
__global__ __launch_bounds__(256) void k_dcn(const float* __restrict__ dcnb){
  extern __shared__ unsigned dynu[];
  unsigned* samp=dynu;                 // [128][36] bf16x2 words
  unsigned* wsm=dynu+128*36;           // [64][36]  bf16x2 words
  unsigned* cwp=wsm+64*36;             // [8][128] packed (w,w)
  int* ci=(int*)(cwp+1024);            // [8][128]
  int b=blockIdx.x>>8,s0=(blockIdx.x&255)<<7,t=threadIdx.x;
  int w=t>>5,l=t&31,mt=w>>1,nh=w&1,lr=l>>2,lc=l&3;
  float acc[8][4];
  for(int j=0;j<8;j++)for(int q=0;q<4;q++)acc[j][q]=0.f;
  const unsigned* at=g_a2bf+(size_t)b*S*32;
  for(int k=0;k<27;k++){
    __syncthreads();
    if(t<128){
      int s=s0+t;
      int z=s>>10,y=(s>>5)&31,x=s&31;
      int kz=k/9,ky=(k/3)%3,kx=k%3;
      float pz=(float)(z+kz-1)+g_off[(b*81+3*k+0)*S+s];
      float py=(float)(y+ky-1)+g_off[(b*81+3*k+1)*S+s];
      float px=(float)(x+kx-1)+g_off[(b*81+3*k+2)*S+s];
      float fz=floorf(pz),fy=floorf(py),fx=floorf(px);
      float wz=pz-fz,wy=py-fy,wx=px-fx;
      int z0=(int)fz,y0=(int)fy,x0=(int)fx;
      #pragma unroll
      for(int cn=0;cn<8;cn++){
        int dz=cn>>2,dy=(cn>>1)&1,dx=cn&1;
        int iz=z0+dz,iy=y0+dy,ix=x0+dx;
        float wv=(dz?wz:1.f-wz)*(dy?wy:1.f-wy)*(dx?wx:1.f-wx);
        bool ok=(unsigned)iz<32u&&(unsigned)iy<32u&&(unsigned)ix<32u;
        int czi=min(max(iz,0),31),cyi=min(max(iy,0),31),cxi=min(max(ix,0),31);
        cwp[cn*128+t]=ok?packbf(wv,wv):0u;
        ci[cn*128+t]=(czi*32+cyi)*32+cxi;
      }
    }
    for(int i=0;i<9;i++){int e=t+256*i;if(e<2304)wsm[e]=g_dcnw_bf[k*2304+e];}
    __syncthreads();
    // gather: thread -> (sp, 8-channel group); uint4 bf16x2 loads, HFMA2 accumulate
    #pragma unroll
    for(int i=0;i<4;i++){
      int e=t+256*i;int sp=e>>3,g=e&7;
      unsigned c0=0,c1=0,c2=0,c3=0;
      #pragma unroll
      for(int cn=0;cn<8;cn++){
        unsigned wv2=cwp[cn*128+sp];
        const uint4 v=*(const uint4*)(at+(size_t)ci[cn*128+sp]*32+g*4);
        c0=bffma(wv2,v.x,c0);c1=bffma(wv2,v.y,c1);
        c2=bffma(wv2,v.z,c2);c3=bffma(wv2,v.w,c3);
      }
      *(uint4*)(samp+sp*36+g*4)=make_uint4(c0,c1,c2,c3);
    }
    __syncthreads();
    int oA=mt*16+lr;
    #pragma unroll
    for(int kc=0;kc<4;kc++){
      unsigned a0=wsm[(oA  )*36+kc*8+lc];
      unsigned a1=wsm[(oA+8)*36+kc*8+lc];
      unsigned a2v=wsm[(oA  )*36+kc*8+lc+4];
      unsigned a3=wsm[(oA+8)*36+kc*8+lc+4];
      #pragma unroll
      for(int j=0;j<8;j++){
        int spc=(nh*8+j)*8+lr;
        unsigned b0=samp[spc*36+kc*8+lc];
        unsigned b1=samp[spc*36+kc*8+lc+4];
        mma16(acc[j],a0,a1,a2v,a3,b0,b1);
      }
    }
  }
  int oA=mt*16+lr;
  float bv0=dcnb[oA],bv1=dcnb[oA+8];
  #pragma unroll
  for(int j=0;j<8;j++){
    int spb=(nh*8+j)*8;
    #pragma unroll
    for(int q=0;q<2;q++){
      int spc=spb+2*lc+q;
      g_dcn[(b*64+oA)*S+s0+spc]=acc[j][q]+bv0;
      g_dcn[(b*64+oA+8)*S+s0+spc]=acc[j][q+2]+bv1;
    }
  }
}

__global__ __launch_bounds__(256) void k_final(const float* __restrict__ n2w,
    const float* __restrict__ n2b,const float* __restrict__ ow,
    const float* __restrict__ ob,float* __restrict__ out){
  __shared__ float Msm[64][65],wsm[64][65],mu[64],rs[64];
  int b=blockIdx.x>>9,g=blockIdx.x&511,t=threadIdx.x;
  for(int i=0;i<16;i++){int e=t+256*i;int r=e>>6,p=e&63;
    Msm[r][p]=g_yfin[(b*64+r)*S+g+(p<<9)];
    wsm[r][p]=ow[e];}
  __syncthreads();
  if(t<64){
    float s1=0.f;
    for(int p=0;p<64;p++)s1+=Msm[t][p];
    float m=s1*(1.f/64.f),sq=0.f;
    for(int p=0;p<64;p++){float d=Msm[t][p]-m;sq+=d*d;}
    mu[t]=m;rs[t]=rsqrtf(sq*(1.f/64.f)+1e-5f);
  }
  __syncthreads();
  for(int i=0;i<16;i++){int e=t+256*i;int r=e>>6,p=e&63;
    Msm[r][p]=(Msm[r][p]-mu[r])*rs[r]*n2w[p]+n2b[p];}
  __syncthreads();
  int og=t&15,sg=t>>4;
  float acc[4][4];
  for(int m=0;m<4;m++)for(int i=0;i<4;i++)acc[m][i]=0.f;
  for(int p=0;p<64;p++){
    float xv[4],wv[4];
    #pragma unroll
    for(int m=0;m<4;m++)xv[m]=Msm[sg+16*m][p];
    #pragma unroll
    for(int i=0;i<4;i++)wv[i]=wsm[og+16*i][p];
    #pragma unroll
    for(int m=0;m<4;m++)
      #pragma unroll
      for(int i=0;i<4;i++)acc[m][i]+=xv[m]*wv[i];
  }
  for(int m=0;m<4;m++){
    int q=(g<<6)+sg+16*m;
    for(int i=0;i<4;i++){
      int o=og+16*i;
      out[(b*S+q)*64+o]=acc[m][i]+ob[o];
    }
  }
}

extern "C" void kernel_launch(void* const* d_in,const int* in_sizes,int n_in,
                              void* d_out,int out_size){
  const float* x   =(const float*)d_in[0];
  const float* temp=(const float*)d_in[1];
  const float* qkvw=(const float*)d_in[2];
  const float* nw  =(const float*)d_in[3];
  const float* nb  =(const float*)d_in[4];
  const float* p1w =(const float*)d_in[5];
  const float* p1b =(const float*)d_in[6];
  const float* c0w =(const float*)d_in[7];
  const float* c0b =(const float*)d_in[8];
  const float* cspw=(const float*)d_in[9];
  const float* cspb=(const float*)d_in[10];
  const float* offw=(const float*)d_in[11];
  const float* offb=(const float*)d_in[12];
  const float* dcnw=(const float*)d_in[13];
  const float* dcnb=(const float*)d_in[14];
  const float* c1w =(const float*)d_in[15];
  const float* c1b =(const float*)d_in[16];
  const float* p2w =(const float*)d_in[17];
  const float* p2b =(const float*)d_in[18];
  const float* n2w =(const float*)d_in[19];
  const float* n2b =(const float*)d_in[20];
  const float* ow  =(const float*)d_in[21];
  const float* ob  =(const float*)d_in[22];
  float* out=(float*)d_out;

  int dcn_smem=(128*36+64*36+1024+1024)*4;  // 35840 B
  cudaFuncSetAttribute(k_dcn,cudaFuncAttributeMaxDynamicSharedMemorySize,dcn_smem);

  k_wprep<<<648,256>>>(offw,dcnw);
  k_qkv<<<1024,256>>>(x,qkvw);
  k_sumsq<<<2048,256>>>();
  k_gram<<<512,256>>>();
  k_softmax<<<8,256>>>(temp);
  k_xca<<<1024,256>>>(nw,nb);
  k_pw<1><<<512,256>>>(0,0,1,p1w,p1b);    // u = gelu(proj1(x5))  (bf16 MMA)
  k_dw5<<<4096,256>>>(1,2,c0w,c0b);       // a1 = dw5(u)
  k_dw7<<<4096,256>>>(2,3,cspw,cspb);     // a2 = dw7(a1)
  k_tr<<<1024,256>>>();                   // a2 -> a2bf (spatial-major bf16)
  k_off<<<1024,256>>>(offb);              // offsets from a2 (bf16 MMA)
  k_dcn<<<512,256,dcn_smem>>>(dcnb);      // deformable conv (bf16 gather + MMA)
  k_pw<2><<<512,256>>>(4,1,2,c1w,c1b);    // a1 = (conv1(dcn)+b)*u (bf16 MMA)
  k_pw<3><<<512,256>>>(2,0,5,p2w,p2b);    // yfin = proj2(a1)+x5   (bf16 MMA)
  k_final<<<1024,256>>>(n2w,n2b,ow,ob,out);
}